// round 3
// baseline (speedup 1.0000x reference)
#include <cuda_runtime.h>
#include <math.h>

#define BB 8
#define SS 2000
#define MM (BB*SS)          // 16000 rows
#define DD 256
#define HH 2
#define HDIM 128
#define FFN 256
#define WIN 99

// ---------------- scratch (device globals; no allocation allowed) ----------
__device__ float g_x   [MM*DD];   // encoder out + pos
__device__ float g_qkv [MM*3*DD]; // packed qkv
__device__ float g_ctx [MM*DD];   // attention context
__device__ float g_att [MM*DD];   // out_proj output
__device__ float g_h1  [MM*DD];   // after LN1
__device__ float g_ff  [MM*FFN];  // relu(ffn1)
__device__ float g_ff2 [MM*DD];   // ffn2
__device__ float g_h2  [MM*DD];   // after LN2
__device__ float g_wc  [260];     // fused head weights (256) + bias (1)

// ---------------- packed fp32x2 helpers (sm_103a FFMA2) --------------------
__device__ __forceinline__ unsigned long long f32x2_dup(float x) {
    unsigned long long r;
    asm("mov.b64 %0, {%1, %1};" : "=l"(r) : "f"(x));
    return r;
}
__device__ __forceinline__ void ffma2(unsigned long long& d,
                                      unsigned long long a,
                                      unsigned long long b) {
    asm("fma.rn.f32x2 %0, %1, %2, %0;" : "+l"(d) : "l"(a), "l"(b));
}

// ---------------- fp32 GEMM, double-buffered, FFMA2 inner loop -------------
// C[m,n] = sum_k A[m,k]*B[n,k] + bias[n]
// A: [M,K] row-major, B: [N,K] row-major (torch Linear weight layout).
// 128x128 tile, TK=16, 256 threads, 8x8 micro-tile (4 f32x2 pairs per row).
// EPI: 0 = bias, 1 = bias + positional encoding, 2 = bias + relu.
#define TM 128
#define TK 16

template<int TN, int EPI, int K>
__global__ void __launch_bounds__(256, 2)
sgemm_kernel(const float* __restrict__ A, const float* __restrict__ B,
             const float* __restrict__ bias, float* __restrict__ C, int N)
{
    constexpr int NT = K / TK;
    __shared__ float As[2][TK][TM + 4];
    __shared__ float Bs[2][TK][TN + 4];

    const int tid  = threadIdx.x;
    const int tx   = tid & 15;         // 0..15 (cols)
    const int ty   = tid >> 4;         // 0..15 (rows)
    const int row0 = blockIdx.x * TM;
    const int col0 = blockIdx.y * TN;
    const int lr   = tid >> 2;         // 0..63
    const int lk   = (tid & 3) * 4;    // 0,4,8,12

    const float* Ap0 = A + (size_t)(row0 + lr) * K + lk;
    const float* Ap1 = Ap0 + (size_t)64 * K;
    const float* Bp0 = B + (size_t)(col0 + lr) * K + lk;
    const float* Bp1 = Bp0 + (size_t)64 * K;

    unsigned long long acc2[8][4];
#pragma unroll
    for (int i = 0; i < 8; i++)
#pragma unroll
        for (int p = 0; p < 4; p++) acc2[i][p] = 0ull;

    // prologue: tile 0 -> regs -> smem buf 0
    float4 ra0 = *(const float4*)Ap0;
    float4 ra1 = *(const float4*)Ap1;
    float4 rb0 = *(const float4*)Bp0;
    float4 rb1 = *(const float4*)Bp1;

    As[0][lk+0][lr] = ra0.x; As[0][lk+1][lr] = ra0.y;
    As[0][lk+2][lr] = ra0.z; As[0][lk+3][lr] = ra0.w;
    As[0][lk+0][lr+64] = ra1.x; As[0][lk+1][lr+64] = ra1.y;
    As[0][lk+2][lr+64] = ra1.z; As[0][lk+3][lr+64] = ra1.w;
    Bs[0][lk+0][lr] = rb0.x; Bs[0][lk+1][lr] = rb0.y;
    Bs[0][lk+2][lr] = rb0.z; Bs[0][lk+3][lr] = rb0.w;
    Bs[0][lk+0][lr+64] = rb1.x; Bs[0][lk+1][lr+64] = rb1.y;
    Bs[0][lk+2][lr+64] = rb1.z; Bs[0][lk+3][lr+64] = rb1.w;
    __syncthreads();

    int buf = 0;
#pragma unroll 1
    for (int t = 0; t < NT; t++) {
        if (t + 1 < NT) {
            const int off = (t + 1) * TK;
            ra0 = *(const float4*)(Ap0 + off);
            ra1 = *(const float4*)(Ap1 + off);
            rb0 = *(const float4*)(Bp0 + off);
            rb1 = *(const float4*)(Bp1 + off);
        }

        const float (*Ac)[TM + 4] = As[buf];
        const float (*Bc)[TN + 4] = Bs[buf];
#pragma unroll
        for (int k = 0; k < TK; k++) {
            float a[8];
            *(float4*)&a[0] = *(const float4*)&Ac[k][ty * 8];
            *(float4*)&a[4] = *(const float4*)&Ac[k][ty * 8 + 4];
            ulonglong2 b01 = *(const ulonglong2*)&Bc[k][tx * 8];
            ulonglong2 b23 = *(const ulonglong2*)&Bc[k][tx * 8 + 4];
            unsigned long long bp[4];
            bp[0] = b01.x; bp[1] = b01.y; bp[2] = b23.x; bp[3] = b23.y;
            unsigned long long ad[8];
#pragma unroll
            for (int i = 0; i < 8; i++) ad[i] = f32x2_dup(a[i]);
#pragma unroll
            for (int i = 0; i < 8; i++)
#pragma unroll
                for (int p = 0; p < 4; p++)
                    ffma2(acc2[i][p], ad[i], bp[p]);
        }

        if (t + 1 < NT) {
            const int nb = buf ^ 1;
            As[nb][lk+0][lr] = ra0.x; As[nb][lk+1][lr] = ra0.y;
            As[nb][lk+2][lr] = ra0.z; As[nb][lk+3][lr] = ra0.w;
            As[nb][lk+0][lr+64] = ra1.x; As[nb][lk+1][lr+64] = ra1.y;
            As[nb][lk+2][lr+64] = ra1.z; As[nb][lk+3][lr+64] = ra1.w;
            Bs[nb][lk+0][lr] = rb0.x; Bs[nb][lk+1][lr] = rb0.y;
            Bs[nb][lk+2][lr] = rb0.z; Bs[nb][lk+3][lr] = rb0.w;
            Bs[nb][lk+0][lr+64] = rb1.x; Bs[nb][lk+1][lr+64] = rb1.y;
            Bs[nb][lk+2][lr+64] = rb1.z; Bs[nb][lk+3][lr+64] = rb1.w;
            __syncthreads();
            buf = nb;
        }
    }

    // epilogue
#pragma unroll
    for (int i = 0; i < 8; i++) {
        const int r = row0 + ty * 8 + i;
#pragma unroll
        for (int p = 0; p < 4; p++) {
            const float2 f = *(const float2*)&acc2[i][p];
#pragma unroll
            for (int q = 0; q < 2; q++) {
                const int c = col0 + tx * 8 + 2 * p + q;
                float v = (q ? f.y : f.x) + bias[c];
                if (EPI == 2) v = fmaxf(v, 0.f);
                if (EPI == 1) {
                    const int s = r % SS;
                    const int pp = c >> 1;
                    const float div = expf(-(float)(2 * pp) * 0.03597789207803197f);
                    const float ang = (float)s * div;
                    v += (c & 1) ? cosf(ang) : sinf(ang);
                }
                C[(size_t)r * N + c] = v;
            }
        }
    }
}

// ---------------- banded attention -----------------------------------------
// Warp handles 2 adjacent queries (i0, i0+1). Lanes split into 8 groups of 4;
// each group handles one key per iteration (4-lane dot split over 128 dims).
// Block = 8 warps = 16 queries; grid = B*H*(S/16).
__global__ void __launch_bounds__(256)
attn_kernel(const float* __restrict__ qkv, float* __restrict__ ctx)
{
    const int w    = threadIdx.x >> 5;
    const int lane = threadIdx.x & 31;
    const int g    = lane >> 2;
    const int s    = lane & 3;

    const int blk = blockIdx.x;
    const int bh  = blk / (SS / 16);
    const int i0  = (blk % (SS / 16)) * 16 + w * 2;
    const int b   = bh >> 1;
    const int h   = bh & 1;

    const float* base = qkv + (size_t)b * SS * (3 * DD);
    const float* Q = base + h * HDIM;
    const float* Kp = base + DD + h * HDIM;
    const float* Vp = base + 2 * DD + h * HDIM;

    // lane covers dim chunks (c*16 + s*4), c = 0..7 (float4 index c*4+s)
    float4 q0r[8], q1r[8];
    {
        const float4* q0p = (const float4*)(Q + (size_t)i0 * (3 * DD));
        const float4* q1p = (const float4*)(Q + (size_t)(i0 + 1) * (3 * DD));
#pragma unroll
        for (int c = 0; c < 8; c++) { q0r[c] = q0p[c * 4 + s]; q1r[c] = q1p[c * 4 + s]; }
    }

    const int js  = (i0 > WIN) ? (i0 - WIN) : 0;
    const int je  = i0 + 1;
    const int T   = (je - js + 1 + 7) >> 3;

    __shared__ float sc0[8][104];
    __shared__ float sc1[8][104];

    // ---- pass 1: scores + running max ----
    float m0 = -1e30f, m1 = -1e30f;
    for (int t = 0; t < T; t++) {
        const int j  = js + t * 8 + g;
        const int jj = t * 8 + g;
        float p0 = 0.f, p1 = 0.f;
        if (j <= je) {
            const float4* kp = (const float4*)(Kp + (size_t)j * (3 * DD));
#pragma unroll
            for (int c = 0; c < 8; c++) {
                float4 k4 = kp[c * 4 + s];
                p0 += q0r[c].x * k4.x + q0r[c].y * k4.y + q0r[c].z * k4.z + q0r[c].w * k4.w;
                p1 += q1r[c].x * k4.x + q1r[c].y * k4.y + q1r[c].z * k4.z + q1r[c].w * k4.w;
            }
        }
        p0 += __shfl_xor_sync(0xffffffffu, p0, 1);
        p0 += __shfl_xor_sync(0xffffffffu, p0, 2);
        p1 += __shfl_xor_sync(0xffffffffu, p1, 1);
        p1 += __shfl_xor_sync(0xffffffffu, p1, 2);
        p0 *= 0.08838834764831845f;
        p1 *= 0.08838834764831845f;
        if (j <= i0) {
            m0 = fmaxf(m0, p0);
            if (s == 0) sc0[w][jj] = p0;
        }
        if (j <= je && j >= i0 - 98) {
            m1 = fmaxf(m1, p1);
            if (s == 0) sc1[w][jj] = p1;
        }
    }
#pragma unroll
    for (int o = 16; o; o >>= 1) {
        m0 = fmaxf(m0, __shfl_xor_sync(0xffffffffu, m0, o));
        m1 = fmaxf(m1, __shfl_xor_sync(0xffffffffu, m1, o));
    }
    __syncwarp();

    // ---- pass 2: exp + sum (invalid slots set to 0) ----
    const int hi0 = i0 - js;
    const int lo1 = (i0 >= 99) ? 1 : 0;
    const int hi1 = je - js;
    float se0 = 0.f, se1 = 0.f;
    for (int jj = lane; jj < T * 8; jj += 32) {
        float r0 = sc0[w][jj];
        float e0 = (jj <= hi0) ? expf(r0 - m0) : 0.f;
        sc0[w][jj] = e0; se0 += e0;
        float r1 = sc1[w][jj];
        float e1 = (jj >= lo1 && jj <= hi1) ? expf(r1 - m1) : 0.f;
        sc1[w][jj] = e1; se1 += e1;
    }
#pragma unroll
    for (int o = 16; o; o >>= 1) {
        se0 += __shfl_xor_sync(0xffffffffu, se0, o);
        se1 += __shfl_xor_sync(0xffffffffu, se1, o);
    }
    __syncwarp();

    // ---- pass 3: weighted V accumulation ----
    float4 a0[8], a1[8];
#pragma unroll
    for (int c = 0; c < 8; c++) {
        a0[c] = make_float4(0.f, 0.f, 0.f, 0.f);
        a1[c] = make_float4(0.f, 0.f, 0.f, 0.f);
    }
    for (int t = 0; t < T; t++) {
        const int j  = js + t * 8 + g;
        const int jj = t * 8 + g;
        if (j <= je) {
            const float p0 = sc0[w][jj];
            const float p1 = sc1[w][jj];
            const float4* vp = (const float4*)(Vp + (size_t)j * (3 * DD));
#pragma unroll
            for (int c = 0; c < 8; c++) {
                float4 v4 = vp[c * 4 + s];
                a0[c].x += p0 * v4.x; a0[c].y += p0 * v4.y;
                a0[c].z += p0 * v4.z; a0[c].w += p0 * v4.w;
                a1[c].x += p1 * v4.x; a1[c].y += p1 * v4.y;
                a1[c].z += p1 * v4.z; a1[c].w += p1 * v4.w;
            }
        }
    }
    // reduce partial ctx across the 8 groups (same s -> same dims)
#pragma unroll
    for (int c = 0; c < 8; c++) {
#pragma unroll
        for (int o = 4; o <= 16; o <<= 1) {
            a0[c].x += __shfl_xor_sync(0xffffffffu, a0[c].x, o);
            a0[c].y += __shfl_xor_sync(0xffffffffu, a0[c].y, o);
            a0[c].z += __shfl_xor_sync(0xffffffffu, a0[c].z, o);
            a0[c].w += __shfl_xor_sync(0xffffffffu, a0[c].w, o);
            a1[c].x += __shfl_xor_sync(0xffffffffu, a1[c].x, o);
            a1[c].y += __shfl_xor_sync(0xffffffffu, a1[c].y, o);
            a1[c].z += __shfl_xor_sync(0xffffffffu, a1[c].z, o);
            a1[c].w += __shfl_xor_sync(0xffffffffu, a1[c].w, o);
        }
    }
    const float inv0 = 1.f / se0;
    const float inv1 = 1.f / se1;
    if (g == 0) {
        float4* o0 = (float4*)(ctx + ((size_t)(b * SS + i0)) * DD + h * HDIM);
        float4* o1 = (float4*)(ctx + ((size_t)(b * SS + i0 + 1)) * DD + h * HDIM);
#pragma unroll
        for (int c = 0; c < 8; c++) {
            float4 r0 = a0[c];
            r0.x *= inv0; r0.y *= inv0; r0.z *= inv0; r0.w *= inv0;
            o0[c * 4 + s] = r0;
            float4 r1 = a1[c];
            r1.x *= inv1; r1.y *= inv1; r1.z *= inv1; r1.w *= inv1;
            o1[c * 4 + s] = r1;
        }
    }
}

// ---------------- residual add + layernorm (row per block, single sync) ----
__global__ void __launch_bounds__(256)
add_ln_kernel(const float* __restrict__ x, const float* __restrict__ y,
              const float* __restrict__ w, const float* __restrict__ b,
              float* __restrict__ out)
{
    const int row = blockIdx.x;
    const int t   = threadIdx.x;
    const size_t idx = (size_t)row * DD + t;
    const float v = x[idx] + y[idx];

    __shared__ float s1[8], s2[8];
    float r = v, q = v * v;
#pragma unroll
    for (int o = 16; o; o >>= 1) {
        r += __shfl_xor_sync(0xffffffffu, r, o);
        q += __shfl_xor_sync(0xffffffffu, q, o);
    }
    if ((t & 31) == 0) { s1[t >> 5] = r; s2[t >> 5] = q; }
    __syncthreads();
    float tot  = s1[0]+s1[1]+s1[2]+s1[3]+s1[4]+s1[5]+s1[6]+s1[7];
    float tot2 = s2[0]+s2[1]+s2[2]+s2[3]+s2[4]+s2[5]+s2[6]+s2[7];
    const float mean = tot * (1.f / DD);
    const float var  = tot2 * (1.f / DD) - mean * mean;
    const float inv  = rsqrtf(var + 1e-5f);

    out[idx] = (v - mean) * inv * w[t] + b[t];
}

// ---------------- fused output head --------------------------------------
__global__ void head_prep_kernel(const float* __restrict__ fc1_w,
                                 const float* __restrict__ fc1_b,
                                 const float* __restrict__ fc2_w,
                                 const float* __restrict__ fc2_b,
                                 float* __restrict__ wc)
{
    const int d = threadIdx.x;   // 256 threads
    float s = 0.f;
#pragma unroll
    for (int j = 0; j < 64; j++) s += fc2_w[j] * fc1_w[j * DD + d];
    wc[d] = s;
    if (d == 0) {
        float bb = fc2_b[0];
        for (int j = 0; j < 64; j++) bb += fc2_w[j] * fc1_b[j];
        wc[256] = bb;
    }
}

__global__ void __launch_bounds__(256)
head_gemv_kernel(const float* __restrict__ h2, const float* __restrict__ wc,
                 float* __restrict__ out)
{
    const int warp = (blockIdx.x * blockDim.x + threadIdx.x) >> 5;
    const int lane = threadIdx.x & 31;
    if (warp >= MM) return;
    const float* r = h2 + (size_t)warp * DD;
    float s = 0.f;
#pragma unroll
    for (int c = 0; c < 8; c++) s += r[lane + 32 * c] * wc[lane + 32 * c];
#pragma unroll
    for (int o = 16; o; o >>= 1) s += __shfl_xor_sync(0xffffffffu, s, o);
    if (lane == 0) out[warp] = s + wc[256];
}

// ---------------- host launch ------------------------------------------------
static float* dptr(const void* sym) {
    void* p = nullptr;
    cudaGetSymbolAddress(&p, sym);
    return (float*)p;
}

extern "C" void kernel_launch(void* const* d_in, const int* in_sizes, int n_in,
                              void* d_out, int out_size)
{
    const float* src        = (const float*)d_in[0];
    const float* W_enc      = (const float*)d_in[2];
    const float* b_enc      = (const float*)d_in[3];
    const float* in_proj_w  = (const float*)d_in[4];
    const float* in_proj_b  = (const float*)d_in[5];
    const float* out_proj_w = (const float*)d_in[6];
    const float* out_proj_b = (const float*)d_in[7];
    const float* ln1_w      = (const float*)d_in[8];
    const float* ln1_b      = (const float*)d_in[9];
    const float* lin1_w     = (const float*)d_in[10];
    const float* lin1_b     = (const float*)d_in[11];
    const float* lin2_w     = (const float*)d_in[12];
    const float* lin2_b     = (const float*)d_in[13];
    const float* ln2_w      = (const float*)d_in[14];
    const float* ln2_b      = (const float*)d_in[15];
    const float* fc1_w      = (const float*)d_in[16];
    const float* fc1_b      = (const float*)d_in[17];
    const float* fc2_w      = (const float*)d_in[18];
    const float* fc2_b      = (const float*)d_in[19];
    float* out = (float*)d_out;

    float* x   = dptr(g_x);
    float* qkv = dptr(g_qkv);
    float* ctx = dptr(g_ctx);
    float* att = dptr(g_att);
    float* h1  = dptr(g_h1);
    float* ff  = dptr(g_ff);
    float* ff2 = dptr(g_ff2);
    float* h2  = dptr(g_h2);
    float* wc  = dptr(g_wc);

    const dim3 blk(256);

    head_prep_kernel<<<1, 256>>>(fc1_w, fc1_b, fc2_w, fc2_b, wc);

    // 1. encoder projection + positional encoding
    sgemm_kernel<128, 1, DD><<<dim3(MM / TM, DD / 128), blk>>>(src, W_enc, b_enc, x, DD);
    // 2. qkv projection
    sgemm_kernel<128, 0, DD><<<dim3(MM / TM, (3 * DD) / 128), blk>>>(x, in_proj_w, in_proj_b, qkv, 3 * DD);
    // 3. banded attention (16 queries per block)
    attn_kernel<<<BB * HH * (SS / 16), blk>>>(qkv, ctx);
    // 4. output projection
    sgemm_kernel<128, 0, DD><<<dim3(MM / TM, DD / 128), blk>>>(ctx, out_proj_w, out_proj_b, att, DD);
    // 5. add + LN1
    add_ln_kernel<<<MM, blk>>>(x, att, ln1_w, ln1_b, h1);
    // 6. ffn1 + relu
    sgemm_kernel<128, 2, DD><<<dim3(MM / TM, FFN / 128), blk>>>(h1, lin1_w, lin1_b, ff, FFN);
    // 7. ffn2
    sgemm_kernel<128, 0, FFN><<<dim3(MM / TM, DD / 128), blk>>>(ff, lin2_w, lin2_b, ff2, DD);
    // 8. add + LN2
    add_ln_kernel<<<MM, blk>>>(h1, ff2, ln2_w, ln2_b, h2);
    // 9. fused head -> logits [B,S]
    head_gemv_kernel<<<(MM * 32 + 255) / 256, blk>>>(h2, wc, out);
}

// round 5
// speedup vs baseline: 1.6249x; 1.6249x over previous
#include <cuda_runtime.h>
#include <cuda_bf16.h>
#include <math.h>
#include <stdint.h>

#define BB 8
#define SS 2000
#define MM (BB*SS)          // 16000 rows
#define DD 256
#define HH 2
#define HDIM 128
#define FFN 256
#define WIN 99
#define KK 256              // all GEMMs have K=256

// ---------------- scratch (device globals; no allocation allowed) ----------
__device__ float g_x   [MM*DD];    // encoder out + pos (fp32, residual)
__device__ float g_qkv [MM*3*DD];  // packed qkv fp32
__device__ float g_att [MM*DD];    // out_proj output fp32
__device__ float g_h1  [MM*DD];    // after LN1 fp32
__device__ float g_ff2 [MM*DD];    // ffn2 fp32
__device__ float g_h2  [MM*DD];    // after LN2 fp32
__device__ float g_wc  [260];      // fused head weights + bias

// bf16 hi/lo activation buffers
__device__ __nv_bfloat16 g_src_hi[MM*DD], g_src_lo[MM*DD];
__device__ __nv_bfloat16 g_x_hi  [MM*DD], g_x_lo  [MM*DD];
__device__ __nv_bfloat16 g_ctx_hi[MM*DD], g_ctx_lo[MM*DD];
__device__ __nv_bfloat16 g_h1_hi [MM*DD], g_h1_lo [MM*DD];
__device__ __nv_bfloat16 g_ff_hi [MM*FFN], g_ff_lo[MM*FFN];

// bf16 hi/lo weights, packed: enc | qkv | outproj | lin1 | lin2  (all [N,256])
#define WOFF_ENC 0
#define WOFF_QKV (256*256)
#define WOFF_OUT (WOFF_QKV + 768*256)
#define WOFF_L1  (WOFF_OUT + 256*256)
#define WOFF_L2  (WOFF_L1  + 256*256)
#define WTOTAL   (WOFF_L2  + 256*256)
__device__ __nv_bfloat16 g_w_hi[WTOTAL], g_w_lo[WTOTAL];

// ======================= PTX helpers ========================================
__device__ __forceinline__ uint32_t smem_u32(const void* p) {
    uint32_t a;
    asm("{ .reg .u64 t; cvta.to.shared.u64 t, %1; cvt.u32.u64 %0, t; }"
        : "=r"(a) : "l"(p));
    return a;
}

__device__ __forceinline__ void mma_bf16(float* c, const uint32_t* a,
                                         const uint32_t* b) {
    asm volatile(
        "mma.sync.aligned.m16n8k16.row.col.f32.bf16.bf16.f32 "
        "{%0,%1,%2,%3}, {%4,%5,%6,%7}, {%8,%9}, {%0,%1,%2,%3};\n"
        : "+f"(c[0]), "+f"(c[1]), "+f"(c[2]), "+f"(c[3])
        : "r"(a[0]), "r"(a[1]), "r"(a[2]), "r"(a[3]), "r"(b[0]), "r"(b[1]));
}

__device__ __forceinline__ void ldsm_x4(uint32_t* r, uint32_t addr) {
    asm volatile("ldmatrix.sync.aligned.m8n8.x4.shared.b16 {%0,%1,%2,%3}, [%4];"
        : "=r"(r[0]), "=r"(r[1]), "=r"(r[2]), "=r"(r[3]) : "r"(addr));
}

#define CPASYNC(dst, src) \
    asm volatile("cp.async.cg.shared.global [%0], [%1], 16;" :: "r"(dst), "l"(src))
#define CPCOMMIT() asm volatile("cp.async.commit_group;" ::: "memory")
#define CPWAIT1()  asm volatile("cp.async.wait_group 1;" ::: "memory")
#define CPWAIT0()  asm volatile("cp.async.wait_group 0;" ::: "memory")

// ======================= tensor-core GEMM (mma.sync bf16 hi/lo) =============
// C[m,n] = sum_k A[m,k]*B[n,k] + bias[n]   (3-pass split: hh + hl + lh)
// Block tile 128x64, 8 warps = 4m x 2n, warp tile 32x32.
// K staged 32 per cp.async stage, double-buffered.
// smem row pitch 40 bf16 (80B) -> conflict-free ldmatrix.
#define SA_HI 0
#define SA_LO 10240
#define SB_HI 20480
#define SB_LO 25600
#define STAGE 30720
#define SM_TOTAL (2*STAGE)

template<int EPI, bool WF32, bool WBF16>
__global__ void __launch_bounds__(256)
mma_gemm(const __nv_bfloat16* __restrict__ Ahi, const __nv_bfloat16* __restrict__ Alo,
         const __nv_bfloat16* __restrict__ Bhi, const __nv_bfloat16* __restrict__ Blo,
         const float* __restrict__ bias, float* __restrict__ outF,
         __nv_bfloat16* __restrict__ outHi, __nv_bfloat16* __restrict__ outLo,
         int Ntot)
{
    extern __shared__ char smem[];
    const uint32_t sb = smem_u32(smem);
    const int tid  = threadIdx.x;
    const int wid  = tid >> 5;
    const int lane = tid & 31;
    const int g    = lane >> 2;
    const int t4   = lane & 3;
    const int wm   = wid & 3;       // 0..3 -> m offset 32*wm
    const int wn   = wid >> 2;      // 0..1 -> n offset 32*wn
    const int row0 = blockIdx.x * 128;
    const int col0 = blockIdx.y * 64;

    float acc[2][4][4];
#pragma unroll
    for (int i = 0; i < 2; i++)
#pragma unroll
        for (int j = 0; j < 4; j++)
#pragma unroll
            for (int k = 0; k < 4; k++) acc[i][j][k] = 0.f;

    // ---- stage issue: k-chunk of 32 into buffer st&1 ----
    auto issue = [&](int st) {
        const int k0 = st * 32;
        const uint32_t base = sb + (st & 1) * STAGE;
#pragma unroll
        for (int z = 0; z < 2; z++) {
            const int q = tid + z * 256;          // 0..511
            const int r = q >> 2, c = q & 3;
            const uint32_t so = r * 80 + c * 16;
            const size_t go = (size_t)(row0 + r) * KK + k0 + c * 8;
            CPASYNC(base + SA_HI + so, Ahi + go);
            CPASYNC(base + SA_LO + so, Alo + go);
        }
        {
            const int r = tid >> 2, c = tid & 3;  // 64 rows x 4 chunks
            const uint32_t so = r * 80 + c * 16;
            const size_t go = (size_t)(col0 + r) * KK + k0 + c * 8;
            CPASYNC(base + SB_HI + so, Bhi + go);
            CPASYNC(base + SB_LO + so, Blo + go);
        }
    };

    issue(0);
    CPCOMMIT();

#pragma unroll 1
    for (int st = 0; st < 8; st++) {
        if (st < 7) { issue(st + 1); CPCOMMIT(); CPWAIT1(); }
        else        { CPWAIT0(); }
        __syncthreads();

        const uint32_t base = sb + (st & 1) * STAGE;
        const int mi = lane >> 3;      // ldmatrix matrix index 0..3
        const int lr = lane & 7;

#pragma unroll
        for (int h = 0; h < 2; h++) {
            uint32_t ah[2][4], al[2][4];
#pragma unroll
            for (int mt = 0; mt < 2; mt++) {
                const int row = wm * 32 + mt * 16 + (mi & 1) * 8 + lr;
                const uint32_t ka = (uint32_t)(h * 16 + (mi >> 1) * 8) * 2;
                ldsm_x4(ah[mt], base + SA_HI + row * 80 + ka);
                ldsm_x4(al[mt], base + SA_LO + row * 80 + ka);
            }
            uint32_t bh[2][4], bl[2][4];
#pragma unroll
            for (int nt2 = 0; nt2 < 2; nt2++) {
                const int row = wn * 32 + nt2 * 16 + (mi >> 1) * 8 + lr;
                const uint32_t kb = (uint32_t)(h * 16 + (mi & 1) * 8) * 2;
                ldsm_x4(bh[nt2], base + SB_HI + row * 80 + kb);
                ldsm_x4(bl[nt2], base + SB_LO + row * 80 + kb);
            }
#pragma unroll
            for (int mt = 0; mt < 2; mt++)
#pragma unroll
                for (int nt = 0; nt < 4; nt++) {
                    const uint32_t* bhp = &bh[nt >> 1][(nt & 1) * 2];
                    const uint32_t* blp = &bl[nt >> 1][(nt & 1) * 2];
                    mma_bf16(acc[mt][nt], ah[mt], bhp);
                    mma_bf16(acc[mt][nt], ah[mt], blp);
                    mma_bf16(acc[mt][nt], al[mt], bhp);
                }
        }
        __syncthreads();
    }

    // ---- epilogue ----
#pragma unroll
    for (int mt = 0; mt < 2; mt++) {
#pragma unroll
        for (int nt = 0; nt < 4; nt++) {
            const int c = col0 + wn * 32 + nt * 8 + t4 * 2;
            const float b0 = bias[c], b1 = bias[c + 1];
#pragma unroll
            for (int half = 0; half < 2; half++) {
                const int r = row0 + wm * 32 + mt * 16 + g + half * 8;
                float v0 = acc[mt][nt][half * 2 + 0] + b0;
                float v1 = acc[mt][nt][half * 2 + 1] + b1;
                if (EPI == 2) { v0 = fmaxf(v0, 0.f); v1 = fmaxf(v1, 0.f); }
                if (EPI == 1) {
                    const int s  = r % SS;
                    const int pp = c >> 1;   // same for c (even) and c+1
                    const float div = expf(-(float)(2 * pp) * 0.03597789207803197f);
                    const float ang = (float)s * div;
                    v0 += sinf(ang);
                    v1 += cosf(ang);
                }
                const size_t o = (size_t)r * Ntot + c;
                if (WF32) *(float2*)(outF + o) = make_float2(v0, v1);
                if (WBF16) {
                    const __nv_bfloat16 h0 = __float2bfloat16(v0);
                    const __nv_bfloat16 h1 = __float2bfloat16(v1);
                    __nv_bfloat162 hp; hp.x = h0; hp.y = h1;
                    *(__nv_bfloat162*)(outHi + o) = hp;
                    __nv_bfloat162 lp;
                    lp.x = __float2bfloat16(v0 - __bfloat162float(h0));
                    lp.y = __float2bfloat16(v1 - __bfloat162float(h1));
                    *(__nv_bfloat162*)(outLo + o) = lp;
                }
            }
        }
    }
}

// ======================= conversions ======================================
__global__ void conv_split_kernel(const float* __restrict__ in,
                                  __nv_bfloat16* __restrict__ hi,
                                  __nv_bfloat16* __restrict__ lo, int n)
{
    const int i = blockIdx.x * blockDim.x + threadIdx.x;
    if (i >= n) return;
    const float v = in[i];
    const __nv_bfloat16 h = __float2bfloat16(v);
    hi[i] = h;
    lo[i] = __float2bfloat16(v - __bfloat162float(h));
}

// ======================= banded attention (fp32 in, bf16 hi/lo out) ========
__global__ void __launch_bounds__(256)
attn_kernel(const float* __restrict__ qkv,
            __nv_bfloat16* __restrict__ chi, __nv_bfloat16* __restrict__ clo)
{
    const int w    = threadIdx.x >> 5;
    const int lane = threadIdx.x & 31;
    const int qb   = blockIdx.x;
    const int bh   = qb / (SS / 8);
    const int i    = (qb % (SS / 8)) * 8 + w;
    const int b    = bh >> 1;
    const int h    = bh & 1;

    const float* base = qkv + (size_t)b * SS * (3 * DD);
    const float4 qv = ((const float4*)(base + (size_t)i * (3 * DD) + h * HDIM))[lane];

    const int jstart = (i > WIN) ? (i - WIN) : 0;
    const int cnt    = i - jstart + 1;

    __shared__ float sc[8][104];

    float mx = -1e30f;
    const float* krow = base + (size_t)jstart * (3 * DD) + DD + h * HDIM;
    for (int jj = 0; jj < cnt; jj++) {
        float4 kv = ((const float4*)(krow + (size_t)jj * (3 * DD)))[lane];
        float p = qv.x * kv.x + qv.y * kv.y + qv.z * kv.z + qv.w * kv.w;
#pragma unroll
        for (int o = 16; o; o >>= 1) p += __shfl_xor_sync(0xffffffffu, p, o);
        p *= 0.08838834764831845f;
        mx = fmaxf(mx, p);
        if (lane == 0) sc[w][jj] = p;
    }
    __syncwarp();

    float se = 0.f;
    for (int jj = lane; jj < cnt; jj += 32) {
        float e = expf(sc[w][jj] - mx);
        sc[w][jj] = e;
        se += e;
    }
    __syncwarp();
#pragma unroll
    for (int o = 16; o; o >>= 1) se += __shfl_xor_sync(0xffffffffu, se, o);

    float4 acc = make_float4(0.f, 0.f, 0.f, 0.f);
    const float* vrow = base + (size_t)jstart * (3 * DD) + 2 * DD + h * HDIM;
    for (int jj = 0; jj < cnt; jj++) {
        const float p = sc[w][jj];
        float4 vv = ((const float4*)(vrow + (size_t)jj * (3 * DD)))[lane];
        acc.x += p * vv.x; acc.y += p * vv.y;
        acc.z += p * vv.z; acc.w += p * vv.w;
    }
    const float inv = 1.f / se;
    const size_t o = ((size_t)(b * SS + i)) * DD + h * HDIM + lane * 4;
    const float f[4] = {acc.x * inv, acc.y * inv, acc.z * inv, acc.w * inv};
#pragma unroll
    for (int t = 0; t < 4; t++) {
        const __nv_bfloat16 hh = __float2bfloat16(f[t]);
        chi[o + t] = hh;
        clo[o + t] = __float2bfloat16(f[t] - __bfloat162float(hh));
    }
}

// ---------------- residual add + layernorm ---------------------------------
template<bool EMIT_BF16>
__global__ void __launch_bounds__(256)
add_ln_kernel(const float* __restrict__ x, const float* __restrict__ y,
              const float* __restrict__ w, const float* __restrict__ b,
              float* __restrict__ out,
              __nv_bfloat16* __restrict__ ohi, __nv_bfloat16* __restrict__ olo)
{
    const int row = blockIdx.x;
    const int t   = threadIdx.x;
    const size_t idx = (size_t)row * DD + t;
    const float v = x[idx] + y[idx];

    __shared__ float s1[8], s2[8];
    float r = v, q = v * v;
#pragma unroll
    for (int o = 16; o; o >>= 1) {
        r += __shfl_xor_sync(0xffffffffu, r, o);
        q += __shfl_xor_sync(0xffffffffu, q, o);
    }
    if ((t & 31) == 0) { s1[t >> 5] = r; s2[t >> 5] = q; }
    __syncthreads();
    float tot  = s1[0]+s1[1]+s1[2]+s1[3]+s1[4]+s1[5]+s1[6]+s1[7];
    float tot2 = s2[0]+s2[1]+s2[2]+s2[3]+s2[4]+s2[5]+s2[6]+s2[7];
    const float mean = tot * (1.f / DD);
    const float var  = tot2 * (1.f / DD) - mean * mean;
    const float inv  = rsqrtf(var + 1e-5f);

    const float ov = (v - mean) * inv * w[t] + b[t];
    out[idx] = ov;
    if (EMIT_BF16) {
        const __nv_bfloat16 hh = __float2bfloat16(ov);
        ohi[idx] = hh;
        olo[idx] = __float2bfloat16(ov - __bfloat162float(hh));
    }
}

// ---------------- fused output head ----------------------------------------
__global__ void head_prep_kernel(const float* __restrict__ fc1_w,
                                 const float* __restrict__ fc1_b,
                                 const float* __restrict__ fc2_w,
                                 const float* __restrict__ fc2_b,
                                 float* __restrict__ wc)
{
    const int d = threadIdx.x;
    float s = 0.f;
#pragma unroll
    for (int j = 0; j < 64; j++) s += fc2_w[j] * fc1_w[j * DD + d];
    wc[d] = s;
    if (d == 0) {
        float bb = fc2_b[0];
        for (int j = 0; j < 64; j++) bb += fc2_w[j] * fc1_b[j];
        wc[256] = bb;
    }
}

__global__ void __launch_bounds__(256)
head_gemv_kernel(const float* __restrict__ h2, const float* __restrict__ wc,
                 float* __restrict__ out)
{
    const int warp = (blockIdx.x * blockDim.x + threadIdx.x) >> 5;
    const int lane = threadIdx.x & 31;
    if (warp >= MM) return;
    const float* r = h2 + (size_t)warp * DD;
    float s = 0.f;
#pragma unroll
    for (int c = 0; c < 8; c++) s += r[lane + 32 * c] * wc[lane + 32 * c];
#pragma unroll
    for (int o = 16; o; o >>= 1) s += __shfl_xor_sync(0xffffffffu, s, o);
    if (lane == 0) out[warp] = s + wc[256];
}

// ---------------- host launch -----------------------------------------------
template<typename T>
static T* dptr(const void* sym) {
    void* p = nullptr;
    cudaGetSymbolAddress(&p, sym);
    return (T*)p;
}

extern "C" void kernel_launch(void* const* d_in, const int* in_sizes, int n_in,
                              void* d_out, int out_size)
{
    const float* src        = (const float*)d_in[0];
    const float* W_enc      = (const float*)d_in[2];
    const float* b_enc      = (const float*)d_in[3];
    const float* in_proj_w  = (const float*)d_in[4];
    const float* in_proj_b  = (const float*)d_in[5];
    const float* out_proj_w = (const float*)d_in[6];
    const float* out_proj_b = (const float*)d_in[7];
    const float* ln1_w      = (const float*)d_in[8];
    const float* ln1_b      = (const float*)d_in[9];
    const float* lin1_w     = (const float*)d_in[10];
    const float* lin1_b     = (const float*)d_in[11];
    const float* lin2_w     = (const float*)d_in[12];
    const float* lin2_b     = (const float*)d_in[13];
    const float* ln2_w      = (const float*)d_in[14];
    const float* ln2_b      = (const float*)d_in[15];
    const float* fc1_w      = (const float*)d_in[16];
    const float* fc1_b      = (const float*)d_in[17];
    const float* fc2_w      = (const float*)d_in[18];
    const float* fc2_b      = (const float*)d_in[19];
    float* out = (float*)d_out;

    float* x   = dptr<float>(g_x);
    float* qkv = dptr<float>(g_qkv);
    float* att = dptr<float>(g_att);
    float* h1  = dptr<float>(g_h1);
    float* ff2 = dptr<float>(g_ff2);
    float* h2  = dptr<float>(g_h2);
    float* wc  = dptr<float>(g_wc);

    __nv_bfloat16* shi = dptr<__nv_bfloat16>(g_src_hi);
    __nv_bfloat16* slo = dptr<__nv_bfloat16>(g_src_lo);
    __nv_bfloat16* xhi = dptr<__nv_bfloat16>(g_x_hi);
    __nv_bfloat16* xlo = dptr<__nv_bfloat16>(g_x_lo);
    __nv_bfloat16* chi = dptr<__nv_bfloat16>(g_ctx_hi);
    __nv_bfloat16* clo = dptr<__nv_bfloat16>(g_ctx_lo);
    __nv_bfloat16* h1hi = dptr<__nv_bfloat16>(g_h1_hi);
    __nv_bfloat16* h1lo = dptr<__nv_bfloat16>(g_h1_lo);
    __nv_bfloat16* ffhi = dptr<__nv_bfloat16>(g_ff_hi);
    __nv_bfloat16* fflo = dptr<__nv_bfloat16>(g_ff_lo);
    __nv_bfloat16* whi = dptr<__nv_bfloat16>(g_w_hi);
    __nv_bfloat16* wlo = dptr<__nv_bfloat16>(g_w_lo);

    cudaFuncSetAttribute(mma_gemm<1, true,  true >, cudaFuncAttributeMaxDynamicSharedMemorySize, SM_TOTAL);
    cudaFuncSetAttribute(mma_gemm<0, true,  false>, cudaFuncAttributeMaxDynamicSharedMemorySize, SM_TOTAL);
    cudaFuncSetAttribute(mma_gemm<2, false, true >, cudaFuncAttributeMaxDynamicSharedMemorySize, SM_TOTAL);

    const dim3 blk(256);

    // weight + src conversions
    conv_split_kernel<<<(256*256 + 255)/256, blk>>>(W_enc,      whi + WOFF_ENC, wlo + WOFF_ENC, 256*256);
    conv_split_kernel<<<(768*256 + 255)/256, blk>>>(in_proj_w,  whi + WOFF_QKV, wlo + WOFF_QKV, 768*256);
    conv_split_kernel<<<(256*256 + 255)/256, blk>>>(out_proj_w, whi + WOFF_OUT, wlo + WOFF_OUT, 256*256);
    conv_split_kernel<<<(256*256 + 255)/256, blk>>>(lin1_w,     whi + WOFF_L1,  wlo + WOFF_L1,  256*256);
    conv_split_kernel<<<(256*256 + 255)/256, blk>>>(lin2_w,     whi + WOFF_L2,  wlo + WOFF_L2,  256*256);
    conv_split_kernel<<<(MM*DD + 255)/256, blk>>>(src, shi, slo, MM*DD);
    head_prep_kernel<<<1, 256>>>(fc1_w, fc1_b, fc2_w, fc2_b, wc);

    // 1. encoder projection + pos  -> x fp32 + hi/lo
    mma_gemm<1, true, true><<<dim3(MM/128, DD/64), blk, SM_TOTAL>>>(
        shi, slo, whi + WOFF_ENC, wlo + WOFF_ENC, b_enc, x, xhi, xlo, DD);
    // 2. qkv projection -> fp32
    mma_gemm<0, true, false><<<dim3(MM/128, (3*DD)/64), blk, SM_TOTAL>>>(
        xhi, xlo, whi + WOFF_QKV, wlo + WOFF_QKV, in_proj_b, qkv, nullptr, nullptr, 3*DD);
    // 3. banded attention -> ctx hi/lo
    attn_kernel<<<BB * HH * (SS / 8), blk>>>(qkv, chi, clo);
    // 4. output projection -> att fp32
    mma_gemm<0, true, false><<<dim3(MM/128, DD/64), blk, SM_TOTAL>>>(
        chi, clo, whi + WOFF_OUT, wlo + WOFF_OUT, out_proj_b, att, nullptr, nullptr, DD);
    // 5. add + LN1 -> h1 fp32 + hi/lo
    add_ln_kernel<true><<<MM, blk>>>(x, att, ln1_w, ln1_b, h1, h1hi, h1lo);
    // 6. ffn1 + relu -> ff hi/lo
    mma_gemm<2, false, true><<<dim3(MM/128, FFN/64), blk, SM_TOTAL>>>(
        h1hi, h1lo, whi + WOFF_L1, wlo + WOFF_L1, lin1_b, nullptr, ffhi, fflo, FFN);
    // 7. ffn2 -> ff2 fp32
    mma_gemm<0, true, false><<<dim3(MM/128, DD/64), blk, SM_TOTAL>>>(
        ffhi, fflo, whi + WOFF_L2, wlo + WOFF_L2, lin2_b, ff2, nullptr, nullptr, DD);
    // 8. add + LN2 -> h2 fp32
    add_ln_kernel<false><<<MM, blk>>>(h1, ff2, ln2_w, ln2_b, h2, nullptr, nullptr);
    // 9. fused head -> logits [B,S]
    head_gemv_kernel<<<(MM * 32 + 255) / 256, blk>>>(h2, wc, out);
}

// round 6
// speedup vs baseline: 2.0722x; 1.2753x over previous
#include <cuda_runtime.h>
#include <cuda_bf16.h>
#include <math.h>
#include <stdint.h>

#define BB 8
#define SS 2000
#define MM (BB*SS)          // 16000 rows
#define DD 256
#define HH 2
#define HDIM 128
#define FFN 256
#define WIN 99
#define KK 256              // all GEMMs have K=256

// ---------------- scratch (device globals; no allocation allowed) ----------
__device__ float g_x   [MM*DD];    // encoder out + pos (fp32, residual)
__device__ float g_qkv [MM*3*DD];  // packed qkv fp32
__device__ float g_att [MM*DD];    // out_proj output fp32
__device__ float g_h1  [MM*DD];    // after LN1 fp32
__device__ float g_ff2 [MM*DD];    // ffn2 fp32
__device__ float g_h2  [MM*DD];    // after LN2 fp32
__device__ float g_wc  [260];      // fused head weights + bias

// bf16 hi/lo activation buffers
__device__ __nv_bfloat16 g_src_hi[MM*DD], g_src_lo[MM*DD];
__device__ __nv_bfloat16 g_x_hi  [MM*DD], g_x_lo  [MM*DD];
__device__ __nv_bfloat16 g_ctx_hi[MM*DD], g_ctx_lo[MM*DD];
__device__ __nv_bfloat16 g_h1_hi [MM*DD], g_h1_lo [MM*DD];
__device__ __nv_bfloat16 g_ff_hi [MM*FFN], g_ff_lo[MM*FFN];

// bf16 hi/lo weights, packed: enc | qkv | outproj | lin1 | lin2  (all [N,256])
#define WOFF_ENC 0
#define WOFF_QKV (256*256)
#define WOFF_OUT (WOFF_QKV + 768*256)
#define WOFF_L1  (WOFF_OUT + 256*256)
#define WOFF_L2  (WOFF_L1  + 256*256)
#define WTOTAL   (WOFF_L2  + 256*256)
__device__ __nv_bfloat16 g_w_hi[WTOTAL], g_w_lo[WTOTAL];

// ======================= PTX helpers ========================================
__device__ __forceinline__ uint32_t smem_u32(const void* p) {
    uint32_t a;
    asm("{ .reg .u64 t; cvta.to.shared.u64 t, %1; cvt.u32.u64 %0, t; }"
        : "=r"(a) : "l"(p));
    return a;
}

__device__ __forceinline__ void mma_bf16(float* c, const uint32_t* a,
                                         const uint32_t* b) {
    asm volatile(
        "mma.sync.aligned.m16n8k16.row.col.f32.bf16.bf16.f32 "
        "{%0,%1,%2,%3}, {%4,%5,%6,%7}, {%8,%9}, {%0,%1,%2,%3};\n"
        : "+f"(c[0]), "+f"(c[1]), "+f"(c[2]), "+f"(c[3])
        : "r"(a[0]), "r"(a[1]), "r"(a[2]), "r"(a[3]), "r"(b[0]), "r"(b[1]));
}

__device__ __forceinline__ void ldsm_x4(uint32_t* r, uint32_t addr) {
    asm volatile("ldmatrix.sync.aligned.m8n8.x4.shared.b16 {%0,%1,%2,%3}, [%4];"
        : "=r"(r[0]), "=r"(r[1]), "=r"(r[2]), "=r"(r[3]) : "r"(addr));
}

#define CPASYNC(dst, src) \
    asm volatile("cp.async.cg.shared.global [%0], [%1], 16;" :: "r"(dst), "l"(src))
#define CPCOMMIT() asm volatile("cp.async.commit_group;" ::: "memory")
#define CPWAIT1()  asm volatile("cp.async.wait_group 1;" ::: "memory")
#define CPWAIT0()  asm volatile("cp.async.wait_group 0;" ::: "memory")

__device__ __forceinline__ void split2(float a, float b, uint32_t& hi, uint32_t& lo) {
    __nv_bfloat16 ha = __float2bfloat16(a), hb = __float2bfloat16(b);
    __nv_bfloat16 la = __float2bfloat16(a - __bfloat162float(ha));
    __nv_bfloat16 lb = __float2bfloat16(b - __bfloat162float(hb));
    hi = ((uint32_t)(*(uint16_t*)&hb) << 16) | (uint32_t)(*(uint16_t*)&ha);
    lo = ((uint32_t)(*(uint16_t*)&lb) << 16) | (uint32_t)(*(uint16_t*)&la);
}

// ======================= tensor-core GEMM (mma.sync bf16 hi/lo) =============
#define SA_HI 0
#define SA_LO 10240
#define SB_HI 20480
#define SB_LO 25600
#define STAGE 30720
#define SM_TOTAL (2*STAGE)

template<int EPI, bool WF32, bool WBF16>
__global__ void __launch_bounds__(256)
mma_gemm(const __nv_bfloat16* __restrict__ Ahi, const __nv_bfloat16* __restrict__ Alo,
         const __nv_bfloat16* __restrict__ Bhi, const __nv_bfloat16* __restrict__ Blo,
         const float* __restrict__ bias, float* __restrict__ outF,
         __nv_bfloat16* __restrict__ outHi, __nv_bfloat16* __restrict__ outLo,
         int Ntot)
{
    extern __shared__ char smem[];
    const uint32_t sb = smem_u32(smem);
    const int tid  = threadIdx.x;
    const int wid  = tid >> 5;
    const int lane = tid & 31;
    const int g    = lane >> 2;
    const int t4   = lane & 3;
    const int wm   = wid & 3;
    const int wn   = wid >> 2;
    const int row0 = blockIdx.x * 128;
    const int col0 = blockIdx.y * 64;

    float acc[2][4][4];
#pragma unroll
    for (int i = 0; i < 2; i++)
#pragma unroll
        for (int j = 0; j < 4; j++)
#pragma unroll
            for (int k = 0; k < 4; k++) acc[i][j][k] = 0.f;

    auto issue = [&](int st) {
        const int k0 = st * 32;
        const uint32_t base = sb + (st & 1) * STAGE;
#pragma unroll
        for (int z = 0; z < 2; z++) {
            const int q = tid + z * 256;
            const int r = q >> 2, c = q & 3;
            const uint32_t so = r * 80 + c * 16;
            const size_t go = (size_t)(row0 + r) * KK + k0 + c * 8;
            CPASYNC(base + SA_HI + so, Ahi + go);
            CPASYNC(base + SA_LO + so, Alo + go);
        }
        {
            const int r = tid >> 2, c = tid & 3;
            const uint32_t so = r * 80 + c * 16;
            const size_t go = (size_t)(col0 + r) * KK + k0 + c * 8;
            CPASYNC(base + SB_HI + so, Bhi + go);
            CPASYNC(base + SB_LO + so, Blo + go);
        }
    };

    issue(0);
    CPCOMMIT();

#pragma unroll 1
    for (int st = 0; st < 8; st++) {
        if (st < 7) { issue(st + 1); CPCOMMIT(); CPWAIT1(); }
        else        { CPWAIT0(); }
        __syncthreads();

        const uint32_t base = sb + (st & 1) * STAGE;
        const int mi = lane >> 3;
        const int lr = lane & 7;

#pragma unroll
        for (int h = 0; h < 2; h++) {
            uint32_t ah[2][4], al[2][4];
#pragma unroll
            for (int mt = 0; mt < 2; mt++) {
                const int row = wm * 32 + mt * 16 + (mi & 1) * 8 + lr;
                const uint32_t ka = (uint32_t)(h * 16 + (mi >> 1) * 8) * 2;
                ldsm_x4(ah[mt], base + SA_HI + row * 80 + ka);
                ldsm_x4(al[mt], base + SA_LO + row * 80 + ka);
            }
            uint32_t bh[2][4], bl[2][4];
#pragma unroll
            for (int nt2 = 0; nt2 < 2; nt2++) {
                const int row = wn * 32 + nt2 * 16 + (mi >> 1) * 8 + lr;
                const uint32_t kb = (uint32_t)(h * 16 + (mi & 1) * 8) * 2;
                ldsm_x4(bh[nt2], base + SB_HI + row * 80 + kb);
                ldsm_x4(bl[nt2], base + SB_LO + row * 80 + kb);
            }
#pragma unroll
            for (int mt = 0; mt < 2; mt++)
#pragma unroll
                for (int nt = 0; nt < 4; nt++) {
                    const uint32_t* bhp = &bh[nt >> 1][(nt & 1) * 2];
                    const uint32_t* blp = &bl[nt >> 1][(nt & 1) * 2];
                    mma_bf16(acc[mt][nt], ah[mt], bhp);
                    mma_bf16(acc[mt][nt], ah[mt], blp);
                    mma_bf16(acc[mt][nt], al[mt], bhp);
                }
        }
        __syncthreads();
    }

#pragma unroll
    for (int mt = 0; mt < 2; mt++) {
#pragma unroll
        for (int nt = 0; nt < 4; nt++) {
            const int c = col0 + wn * 32 + nt * 8 + t4 * 2;
            const float b0 = bias[c], b1 = bias[c + 1];
#pragma unroll
            for (int half = 0; half < 2; half++) {
                const int r = row0 + wm * 32 + mt * 16 + g + half * 8;
                float v0 = acc[mt][nt][half * 2 + 0] + b0;
                float v1 = acc[mt][nt][half * 2 + 1] + b1;
                if (EPI == 2) { v0 = fmaxf(v0, 0.f); v1 = fmaxf(v1, 0.f); }
                if (EPI == 1) {
                    const int s  = r % SS;
                    const int pp = c >> 1;
                    const float div = expf(-(float)(2 * pp) * 0.03597789207803197f);
                    const float ang = (float)s * div;
                    v0 += sinf(ang);
                    v1 += cosf(ang);
                }
                const size_t o = (size_t)r * Ntot + c;
                if (WF32) *(float2*)(outF + o) = make_float2(v0, v1);
                if (WBF16) {
                    uint32_t hp, lp;
                    split2(v0, v1, hp, lp);
                    *(uint32_t*)(outHi + o) = hp;
                    *(uint32_t*)(outLo + o) = lp;
                }
            }
        }
    }
}

// ======================= conversions ======================================
__global__ void conv_split_kernel(const float* __restrict__ in,
                                  __nv_bfloat16* __restrict__ hi,
                                  __nv_bfloat16* __restrict__ lo, int n)
{
    const int i = blockIdx.x * blockDim.x + threadIdx.x;
    if (i >= n) return;
    const float v = in[i];
    const __nv_bfloat16 h = __float2bfloat16(v);
    hi[i] = h;
    lo[i] = __float2bfloat16(v - __bfloat162float(h));
}

// ======================= flash-style banded attention =======================
// Block: one (b,h) x 64 queries, 4 warps (16 rows each).
// Keys jj in [0,192) with j_abs = i0-99+jj, 3 tiles of 64.
// QK and PV both bf16 hi/lo 3-pass mma; running softmax in registers.
#define FQH 0
#define FQL 17408
#define FKH 34816
#define FKL 52224
#define FVH 69632
#define FVL 88064
#define FSM_TOTAL 106496

__global__ void __launch_bounds__(128)
flash_attn_kernel(const float* __restrict__ qkv,
                  __nv_bfloat16* __restrict__ chi, __nv_bfloat16* __restrict__ clo)
{
    extern __shared__ char sm[];
    const uint32_t sb = smem_u32(sm);
    const int tid  = threadIdx.x;
    const int w    = tid >> 5;
    const int lane = tid & 31;
    const int g    = lane >> 2;
    const int t4   = lane & 3;
    const int mi   = lane >> 3;
    const int lr   = lane & 7;

    const int i0 = blockIdx.x * 64;
    const int b  = blockIdx.y >> 1;
    const int h  = blockIdx.y & 1;
    const int kstart = i0 - 99;
    const float* base = qkv + (size_t)b * SS * 768;

    // ---- load Q (scaled by 1/sqrt(128)) -> smem hi/lo, pitch 136 elems ----
    {
        const int r  = tid >> 1;
        const int d0 = (tid & 1) * 64;
        const int i  = min(i0 + r, SS - 1);
        const float* qr = base + (size_t)i * 768 + h * 128 + d0;
        const uint32_t so = (uint32_t)r * 272 + (uint32_t)d0 * 2;
#pragma unroll
        for (int c = 0; c < 16; c++) {
            float4 v = *(const float4*)(qr + c * 4);
            v.x *= 0.08838834764831845f; v.y *= 0.08838834764831845f;
            v.z *= 0.08838834764831845f; v.w *= 0.08838834764831845f;
            uint32_t h0, l0, h1, l1;
            split2(v.x, v.y, h0, l0);
            split2(v.z, v.w, h1, l1);
            *(uint32_t*)(sm + FQH + so + c * 8)     = h0;
            *(uint32_t*)(sm + FQH + so + c * 8 + 4) = h1;
            *(uint32_t*)(sm + FQL + so + c * 8)     = l0;
            *(uint32_t*)(sm + FQL + so + c * 8 + 4) = l1;
        }
    }

    float ctx[16][4];
#pragma unroll
    for (int i = 0; i < 16; i++)
#pragma unroll
        for (int j = 0; j < 4; j++) ctx[i][j] = 0.f;

    const int qi0 = w * 16 + g;
    const int qi1 = qi0 + 8;
    const int vlo0 = max(qi0, 99 - i0), vhi0 = qi0 + 99;
    const int vlo1 = max(qi1, 99 - i0), vhi1 = qi1 + 99;
    float m0 = -1e30f, m1 = -1e30f, L0 = 0.f, L1 = 0.f;

#pragma unroll 1
    for (int tt = 0; tt < 3; tt++) {
        __syncthreads();
        // ---- load K tile [64][136] hi/lo ----
        {
            const int r  = tid >> 1;
            const int d0 = (tid & 1) * 64;
            const int j  = min(max(kstart + tt * 64 + r, 0), SS - 1);
            const float* kr = base + (size_t)j * 768 + 256 + h * 128 + d0;
            const uint32_t so = (uint32_t)r * 272 + (uint32_t)d0 * 2;
#pragma unroll
            for (int c = 0; c < 16; c++) {
                float4 v = *(const float4*)(kr + c * 4);
                uint32_t h0, l0, h1, l1;
                split2(v.x, v.y, h0, l0);
                split2(v.z, v.w, h1, l1);
                *(uint32_t*)(sm + FKH + so + c * 8)     = h0;
                *(uint32_t*)(sm + FKH + so + c * 8 + 4) = h1;
                *(uint32_t*)(sm + FKL + so + c * 8)     = l0;
                *(uint32_t*)(sm + FKL + so + c * 8 + 4) = l1;
            }
        }
        // ---- load V tile transposed -> [d 0..127][j 0..63], pitch 72 ----
        {
            const int r  = tid >> 1;          // j local
            const int d0 = (tid & 1) * 64;
            const int j  = min(max(kstart + tt * 64 + r, 0), SS - 1);
            const float* vr = base + (size_t)j * 768 + 512 + h * 128 + d0;
#pragma unroll
            for (int c = 0; c < 16; c++) {
                float4 v = *(const float4*)(vr + c * 4);
                const float vv[4] = {v.x, v.y, v.z, v.w};
#pragma unroll
                for (int t = 0; t < 4; t++) {
                    const int d = d0 + c * 4 + t;
                    const __nv_bfloat16 hv = __float2bfloat16(vv[t]);
                    const __nv_bfloat16 lv = __float2bfloat16(vv[t] - __bfloat162float(hv));
                    *(__nv_bfloat16*)(sm + FVH + d * 144 + r * 2) = hv;
                    *(__nv_bfloat16*)(sm + FVL + d * 144 + r * 2) = lv;
                }
            }
        }
        __syncthreads();

        // ---- QK: S[8][4] over 64 keys ----
        float S[8][4];
#pragma unroll
        for (int i = 0; i < 8; i++)
#pragma unroll
            for (int j = 0; j < 4; j++) S[i][j] = 0.f;

#pragma unroll
        for (int kb = 0; kb < 8; kb++) {
            uint32_t aqh[4], aql[4];
            const uint32_t arow = (uint32_t)(w * 16 + (mi & 1) * 8 + lr) * 272
                                + (uint32_t)(kb * 16 + (mi >> 1) * 8) * 2;
            ldsm_x4(aqh, sb + FQH + arow);
            ldsm_x4(aql, sb + FQL + arow);
#pragma unroll
            for (int nbp = 0; nbp < 4; nbp++) {
                uint32_t bkh[4], bkl[4];
                const uint32_t brow = (uint32_t)(nbp * 16 + (mi >> 1) * 8 + lr) * 272
                                    + (uint32_t)(kb * 16 + (mi & 1) * 8) * 2;
                ldsm_x4(bkh, sb + FKH + brow);
                ldsm_x4(bkl, sb + FKL + brow);
                mma_bf16(S[nbp * 2],     aqh, &bkh[0]);
                mma_bf16(S[nbp * 2 + 1], aqh, &bkh[2]);
                mma_bf16(S[nbp * 2],     aqh, &bkl[0]);
                mma_bf16(S[nbp * 2 + 1], aqh, &bkl[2]);
                mma_bf16(S[nbp * 2],     aql, &bkh[0]);
                mma_bf16(S[nbp * 2 + 1], aql, &bkh[2]);
            }
        }

        // ---- band mask + running softmax ----
        float mx0 = -1e30f, mx1 = -1e30f;
#pragma unroll
        for (int nb = 0; nb < 8; nb++) {
            const int jj = tt * 64 + nb * 8 + t4 * 2;
            if (jj < vlo0     || jj > vhi0)     S[nb][0] = -1e30f;
            if (jj + 1 < vlo0 || jj + 1 > vhi0) S[nb][1] = -1e30f;
            if (jj < vlo1     || jj > vhi1)     S[nb][2] = -1e30f;
            if (jj + 1 < vlo1 || jj + 1 > vhi1) S[nb][3] = -1e30f;
            mx0 = fmaxf(mx0, fmaxf(S[nb][0], S[nb][1]));
            mx1 = fmaxf(mx1, fmaxf(S[nb][2], S[nb][3]));
        }
        mx0 = fmaxf(mx0, __shfl_xor_sync(0xffffffffu, mx0, 1));
        mx0 = fmaxf(mx0, __shfl_xor_sync(0xffffffffu, mx0, 2));
        mx1 = fmaxf(mx1, __shfl_xor_sync(0xffffffffu, mx1, 1));
        mx1 = fmaxf(mx1, __shfl_xor_sync(0xffffffffu, mx1, 2));

        const float mn0 = fmaxf(m0, mx0);
        const float mn1 = fmaxf(m1, mx1);
        const float f0 = __expf(m0 - mn0);
        const float f1 = __expf(m1 - mn1);

        float sum0 = 0.f, sum1 = 0.f;
#pragma unroll
        for (int nb = 0; nb < 8; nb++) {
            float e0 = (S[nb][0] == -1e30f) ? 0.f : __expf(S[nb][0] - mn0);
            float e1 = (S[nb][1] == -1e30f) ? 0.f : __expf(S[nb][1] - mn0);
            float e2 = (S[nb][2] == -1e30f) ? 0.f : __expf(S[nb][2] - mn1);
            float e3 = (S[nb][3] == -1e30f) ? 0.f : __expf(S[nb][3] - mn1);
            S[nb][0] = e0; S[nb][1] = e1; S[nb][2] = e2; S[nb][3] = e3;
            sum0 += e0 + e1;
            sum1 += e2 + e3;
        }
        sum0 += __shfl_xor_sync(0xffffffffu, sum0, 1);
        sum0 += __shfl_xor_sync(0xffffffffu, sum0, 2);
        sum1 += __shfl_xor_sync(0xffffffffu, sum1, 1);
        sum1 += __shfl_xor_sync(0xffffffffu, sum1, 2);
        L0 = L0 * f0 + sum0;
        L1 = L1 * f1 + sum1;
        m0 = mn0; m1 = mn1;

#pragma unroll
        for (int nb = 0; nb < 16; nb++) {
            ctx[nb][0] *= f0; ctx[nb][1] *= f0;
            ctx[nb][2] *= f1; ctx[nb][3] *= f1;
        }

        // ---- PV: P fragments straight from S registers ----
#pragma unroll
        for (int kb2 = 0; kb2 < 4; kb2++) {
            uint32_t ahi[4], alo[4];
            split2(S[2 * kb2][0],     S[2 * kb2][1],     ahi[0], alo[0]);
            split2(S[2 * kb2][2],     S[2 * kb2][3],     ahi[1], alo[1]);
            split2(S[2 * kb2 + 1][0], S[2 * kb2 + 1][1], ahi[2], alo[2]);
            split2(S[2 * kb2 + 1][2], S[2 * kb2 + 1][3], ahi[3], alo[3]);
#pragma unroll
            for (int dbp = 0; dbp < 8; dbp++) {
                uint32_t bvh[4], bvl[4];
                const uint32_t vrow = (uint32_t)(dbp * 16 + (mi >> 1) * 8 + lr) * 144
                                    + (uint32_t)(kb2 * 16 + (mi & 1) * 8) * 2;
                ldsm_x4(bvh, sb + FVH + vrow);
                ldsm_x4(bvl, sb + FVL + vrow);
                mma_bf16(ctx[dbp * 2],     ahi, &bvh[0]);
                mma_bf16(ctx[dbp * 2 + 1], ahi, &bvh[2]);
                mma_bf16(ctx[dbp * 2],     ahi, &bvl[0]);
                mma_bf16(ctx[dbp * 2 + 1], ahi, &bvl[2]);
                mma_bf16(ctx[dbp * 2],     alo, &bvh[0]);
                mma_bf16(ctx[dbp * 2 + 1], alo, &bvh[2]);
            }
        }
    }

    // ---- store ctx / L ----
    const float inv0 = 1.f / L0;
    const float inv1 = 1.f / L1;
    const int ig0 = i0 + qi0;
    const int ig1 = i0 + qi1;
    if (ig0 < SS) {
        const size_t ro = (size_t)(b * SS + ig0) * DD + h * HDIM;
#pragma unroll
        for (int nb = 0; nb < 16; nb++) {
            const int d = nb * 8 + t4 * 2;
            uint32_t hp, lp;
            split2(ctx[nb][0] * inv0, ctx[nb][1] * inv0, hp, lp);
            *(uint32_t*)(chi + ro + d) = hp;
            *(uint32_t*)(clo + ro + d) = lp;
        }
    }
    if (ig1 < SS) {
        const size_t ro = (size_t)(b * SS + ig1) * DD + h * HDIM;
#pragma unroll
        for (int nb = 0; nb < 16; nb++) {
            const int d = nb * 8 + t4 * 2;
            uint32_t hp, lp;
            split2(ctx[nb][2] * inv1, ctx[nb][3] * inv1, hp, lp);
            *(uint32_t*)(chi + ro + d) = hp;
            *(uint32_t*)(clo + ro + d) = lp;
        }
    }
}

// ---------------- residual add + layernorm ---------------------------------
template<bool EMIT_BF16>
__global__ void __launch_bounds__(256)
add_ln_kernel(const float* __restrict__ x, const float* __restrict__ y,
              const float* __restrict__ w, const float* __restrict__ b,
              float* __restrict__ out,
              __nv_bfloat16* __restrict__ ohi, __nv_bfloat16* __restrict__ olo)
{
    const int row = blockIdx.x;
    const int t   = threadIdx.x;
    const size_t idx = (size_t)row * DD + t;
    const float v = x[idx] + y[idx];

    __shared__ float s1[8], s2[8];
    float r = v, q = v * v;
#pragma unroll
    for (int o = 16; o; o >>= 1) {
        r += __shfl_xor_sync(0xffffffffu, r, o);
        q += __shfl_xor_sync(0xffffffffu, q, o);
    }
    if ((t & 31) == 0) { s1[t >> 5] = r; s2[t >> 5] = q; }
    __syncthreads();
    float tot  = s1[0]+s1[1]+s1[2]+s1[3]+s1[4]+s1[5]+s1[6]+s1[7];
    float tot2 = s2[0]+s2[1]+s2[2]+s2[3]+s2[4]+s2[5]+s2[6]+s2[7];
    const float mean = tot * (1.f / DD);
    const float var  = tot2 * (1.f / DD) - mean * mean;
    const float inv  = rsqrtf(var + 1e-5f);

    const float ov = (v - mean) * inv * w[t] + b[t];
    out[idx] = ov;
    if (EMIT_BF16) {
        const __nv_bfloat16 hh = __float2bfloat16(ov);
        ohi[idx] = hh;
        olo[idx] = __float2bfloat16(ov - __bfloat162float(hh));
    }
}

// ---------------- fused output head ----------------------------------------
__global__ void head_prep_kernel(const float* __restrict__ fc1_w,
                                 const float* __restrict__ fc1_b,
                                 const float* __restrict__ fc2_w,
                                 const float* __restrict__ fc2_b,
                                 float* __restrict__ wc)
{
    const int d = threadIdx.x;
    float s = 0.f;
#pragma unroll
    for (int j = 0; j < 64; j++) s += fc2_w[j] * fc1_w[j * DD + d];
    wc[d] = s;
    if (d == 0) {
        float bb = fc2_b[0];
        for (int j = 0; j < 64; j++) bb += fc2_w[j] * fc1_b[j];
        wc[256] = bb;
    }
}

__global__ void __launch_bounds__(256)
head_gemv_kernel(const float* __restrict__ h2, const float* __restrict__ wc,
                 float* __restrict__ out)
{
    const int warp = (blockIdx.x * blockDim.x + threadIdx.x) >> 5;
    const int lane = threadIdx.x & 31;
    if (warp >= MM) return;
    const float* r = h2 + (size_t)warp * DD;
    float s = 0.f;
#pragma unroll
    for (int c = 0; c < 8; c++) s += r[lane + 32 * c] * wc[lane + 32 * c];
#pragma unroll
    for (int o = 16; o; o >>= 1) s += __shfl_xor_sync(0xffffffffu, s, o);
    if (lane == 0) out[warp] = s + wc[256];
}

// ---------------- host launch -----------------------------------------------
template<typename T>
static T* dptr(const void* sym) {
    void* p = nullptr;
    cudaGetSymbolAddress(&p, sym);
    return (T*)p;
}

extern "C" void kernel_launch(void* const* d_in, const int* in_sizes, int n_in,
                              void* d_out, int out_size)
{
    const float* src        = (const float*)d_in[0];
    const float* W_enc      = (const float*)d_in[2];
    const float* b_enc      = (const float*)d_in[3];
    const float* in_proj_w  = (const float*)d_in[4];
    const float* in_proj_b  = (const float*)d_in[5];
    const float* out_proj_w = (const float*)d_in[6];
    const float* out_proj_b = (const float*)d_in[7];
    const float* ln1_w      = (const float*)d_in[8];
    const float* ln1_b      = (const float*)d_in[9];
    const float* lin1_w     = (const float*)d_in[10];
    const float* lin1_b     = (const float*)d_in[11];
    const float* lin2_w     = (const float*)d_in[12];
    const float* lin2_b     = (const float*)d_in[13];
    const float* ln2_w      = (const float*)d_in[14];
    const float* ln2_b      = (const float*)d_in[15];
    const float* fc1_w      = (const float*)d_in[16];
    const float* fc1_b      = (const float*)d_in[17];
    const float* fc2_w      = (const float*)d_in[18];
    const float* fc2_b      = (const float*)d_in[19];
    float* out = (float*)d_out;

    float* x   = dptr<float>(g_x);
    float* qkv = dptr<float>(g_qkv);
    float* att = dptr<float>(g_att);
    float* h1  = dptr<float>(g_h1);
    float* ff2 = dptr<float>(g_ff2);
    float* h2  = dptr<float>(g_h2);
    float* wc  = dptr<float>(g_wc);

    __nv_bfloat16* shi = dptr<__nv_bfloat16>(g_src_hi);
    __nv_bfloat16* slo = dptr<__nv_bfloat16>(g_src_lo);
    __nv_bfloat16* xhi = dptr<__nv_bfloat16>(g_x_hi);
    __nv_bfloat16* xlo = dptr<__nv_bfloat16>(g_x_lo);
    __nv_bfloat16* chi = dptr<__nv_bfloat16>(g_ctx_hi);
    __nv_bfloat16* clo = dptr<__nv_bfloat16>(g_ctx_lo);
    __nv_bfloat16* h1hi = dptr<__nv_bfloat16>(g_h1_hi);
    __nv_bfloat16* h1lo = dptr<__nv_bfloat16>(g_h1_lo);
    __nv_bfloat16* ffhi = dptr<__nv_bfloat16>(g_ff_hi);
    __nv_bfloat16* fflo = dptr<__nv_bfloat16>(g_ff_lo);
    __nv_bfloat16* whi = dptr<__nv_bfloat16>(g_w_hi);
    __nv_bfloat16* wlo = dptr<__nv_bfloat16>(g_w_lo);

    cudaFuncSetAttribute(mma_gemm<1, true,  true >, cudaFuncAttributeMaxDynamicSharedMemorySize, SM_TOTAL);
    cudaFuncSetAttribute(mma_gemm<0, true,  false>, cudaFuncAttributeMaxDynamicSharedMemorySize, SM_TOTAL);
    cudaFuncSetAttribute(mma_gemm<2, false, true >, cudaFuncAttributeMaxDynamicSharedMemorySize, SM_TOTAL);
    cudaFuncSetAttribute(flash_attn_kernel, cudaFuncAttributeMaxDynamicSharedMemorySize, FSM_TOTAL);

    const dim3 blk(256);

    // weight + src conversions
    conv_split_kernel<<<(256*256 + 255)/256, blk>>>(W_enc,      whi + WOFF_ENC, wlo + WOFF_ENC, 256*256);
    conv_split_kernel<<<(768*256 + 255)/256, blk>>>(in_proj_w,  whi + WOFF_QKV, wlo + WOFF_QKV, 768*256);
    conv_split_kernel<<<(256*256 + 255)/256, blk>>>(out_proj_w, whi + WOFF_OUT, wlo + WOFF_OUT, 256*256);
    conv_split_kernel<<<(256*256 + 255)/256, blk>>>(lin1_w,     whi + WOFF_L1,  wlo + WOFF_L1,  256*256);
    conv_split_kernel<<<(256*256 + 255)/256, blk>>>(lin2_w,     whi + WOFF_L2,  wlo + WOFF_L2,  256*256);
    conv_split_kernel<<<(MM*DD + 255)/256, blk>>>(src, shi, slo, MM*DD);
    head_prep_kernel<<<1, 256>>>(fc1_w, fc1_b, fc2_w, fc2_b, wc);

    // 1. encoder projection + pos  -> x fp32 + hi/lo
    mma_gemm<1, true, true><<<dim3(MM/128, DD/64), blk, SM_TOTAL>>>(
        shi, slo, whi + WOFF_ENC, wlo + WOFF_ENC, b_enc, x, xhi, xlo, DD);
    // 2. qkv projection -> fp32
    mma_gemm<0, true, false><<<dim3(MM/128, (3*DD)/64), blk, SM_TOTAL>>>(
        xhi, xlo, whi + WOFF_QKV, wlo + WOFF_QKV, in_proj_b, qkv, nullptr, nullptr, 3*DD);
    // 3. flash banded attention -> ctx hi/lo
    flash_attn_kernel<<<dim3(32, BB*HH), 128, FSM_TOTAL>>>(qkv, chi, clo);
    // 4. output projection -> att fp32
    mma_gemm<0, true, false><<<dim3(MM/128, DD/64), blk, SM_TOTAL>>>(
        chi, clo, whi + WOFF_OUT, wlo + WOFF_OUT, out_proj_b, att, nullptr, nullptr, DD);
    // 5. add + LN1 -> h1 fp32 + hi/lo
    add_ln_kernel<true><<<MM, blk>>>(x, att, ln1_w, ln1_b, h1, h1hi, h1lo);
    // 6. ffn1 + relu -> ff hi/lo
    mma_gemm<2, false, true><<<dim3(MM/128, FFN/64), blk, SM_TOTAL>>>(
        h1hi, h1lo, whi + WOFF_L1, wlo + WOFF_L1, lin1_b, nullptr, ffhi, fflo, FFN);
    // 7. ffn2 -> ff2 fp32
    mma_gemm<0, true, false><<<dim3(MM/128, DD/64), blk, SM_TOTAL>>>(
        ffhi, fflo, whi + WOFF_L2, wlo + WOFF_L2, lin2_b, ff2, nullptr, nullptr, DD);
    // 8. add + LN2 -> h2 fp32
    add_ln_kernel<false><<<MM, blk>>>(h1, ff2, ln2_w, ln2_b, h2, nullptr, nullptr);
    // 9. fused head -> logits [B,S]
    head_gemv_kernel<<<(MM * 32 + 255) / 256, blk>>>(h2, wc, out);
}

// round 7
// speedup vs baseline: 2.3692x; 1.1434x over previous
#include <cuda_runtime.h>
#include <cuda_bf16.h>
#include <math.h>
#include <stdint.h>

#define BB 8
#define SS 2000
#define MM (BB*SS)          // 16000 rows
#define DD 256
#define HH 2
#define HDIM 128
#define FFN 256
#define WIN 99
#define KK 256              // all GEMMs have K=256

// ---------------- scratch (device globals; no allocation allowed) ----------
__device__ float g_src [MM*DD];    // tf32-rounded src
__device__ float g_x   [MM*DD];    // encoder out + pos (rounded)
__device__ float g_qkv [MM*3*DD];  // packed qkv (rounded)
__device__ float g_ctx [MM*DD];    // attention context (rounded)
__device__ float g_att [MM*DD];    // out_proj output
__device__ float g_h1  [MM*DD];    // after LN1 (rounded)
__device__ float g_ff  [MM*FFN];   // relu(ffn1) (rounded)
__device__ float g_ff2 [MM*DD];    // ffn2
__device__ float g_h2  [MM*DD];    // after LN2
__device__ float g_wc  [260];      // fused head weights + bias
__device__ float g_pos [SS*DD];    // positional encoding table

// tf32-rounded weights, packed: enc | qkv | outproj | lin1 | lin2 (all [N,256])
#define WOFF_ENC 0
#define WOFF_QKV 65536
#define WOFF_OUT 262144
#define WOFF_L1  327680
#define WOFF_L2  393216
#define WTOTAL   458752
__device__ float g_w[WTOTAL];

// ======================= PTX helpers ========================================
__device__ __forceinline__ uint32_t smem_u32(const void* p) {
    uint32_t a;
    asm("{ .reg .u64 t; cvta.to.shared.u64 t, %1; cvt.u32.u64 %0, t; }"
        : "=r"(a) : "l"(p));
    return a;
}

__device__ __forceinline__ float tf32r(float x) {
    uint32_t u;
    asm("cvt.rna.tf32.f32 %0, %1;" : "=r"(u) : "f"(x));
    return __uint_as_float(u);
}

__device__ __forceinline__ void mma_tf32(float* c, const uint32_t* a,
                                         const uint32_t* b) {
    asm volatile(
        "mma.sync.aligned.m16n8k8.row.col.f32.tf32.tf32.f32 "
        "{%0,%1,%2,%3}, {%4,%5,%6,%7}, {%8,%9}, {%0,%1,%2,%3};\n"
        : "+f"(c[0]), "+f"(c[1]), "+f"(c[2]), "+f"(c[3])
        : "r"(a[0]), "r"(a[1]), "r"(a[2]), "r"(a[3]), "r"(b[0]), "r"(b[1]));
}

__device__ __forceinline__ void mma_bf16(float* c, const uint32_t* a,
                                         const uint32_t* b) {
    asm volatile(
        "mma.sync.aligned.m16n8k16.row.col.f32.bf16.bf16.f32 "
        "{%0,%1,%2,%3}, {%4,%5,%6,%7}, {%8,%9}, {%0,%1,%2,%3};\n"
        : "+f"(c[0]), "+f"(c[1]), "+f"(c[2]), "+f"(c[3])
        : "r"(a[0]), "r"(a[1]), "r"(a[2]), "r"(a[3]), "r"(b[0]), "r"(b[1]));
}

__device__ __forceinline__ void ldsm_x4(uint32_t* r, uint32_t addr) {
    asm volatile("ldmatrix.sync.aligned.m8n8.x4.shared.b16 {%0,%1,%2,%3}, [%4];"
        : "=r"(r[0]), "=r"(r[1]), "=r"(r[2]), "=r"(r[3]) : "r"(addr));
}

#define CPASYNC(dst, src) \
    asm volatile("cp.async.cg.shared.global [%0], [%1], 16;" :: "r"(dst), "l"(src))
#define CPCOMMIT() asm volatile("cp.async.commit_group;" ::: "memory")
#define CPWAIT1()  asm volatile("cp.async.wait_group 1;" ::: "memory")
#define CPWAIT0()  asm volatile("cp.async.wait_group 0;" ::: "memory")

__device__ __forceinline__ void split2(float a, float b, uint32_t& hi, uint32_t& lo) {
    __nv_bfloat16 ha = __float2bfloat16(a), hb = __float2bfloat16(b);
    __nv_bfloat16 la = __float2bfloat16(a - __bfloat162float(ha));
    __nv_bfloat16 lb = __float2bfloat16(b - __bfloat162float(hb));
    hi = ((uint32_t)(*(uint16_t*)&hb) << 16) | (uint32_t)(*(uint16_t*)&ha);
    lo = ((uint32_t)(*(uint16_t*)&lb) << 16) | (uint32_t)(*(uint16_t*)&la);
}

// ======================= tf32 single-pass GEMM =============================
// C[m,n] = sum_k A[m,k]*B[n,k] + bias[n]; A,B pre-rounded to tf32 bits.
// Block tile 128x64, 8 warps = 4m x 2n, warp tile 32x32.
// K staged 32 per cp.async stage, double-buffered. smem pitch 36 floats.
// EPI: 0 bias, 1 bias + pos table, 2 bias + relu. Output tf32-rounded.
#define PITCHB 144          // 36 floats
#define TSA 0
#define TSB 18432
#define TSTAGE 27648
#define TSM_TOTAL (2*TSTAGE)

template<int EPI>
__global__ void __launch_bounds__(256)
tf32_gemm(const float* __restrict__ A, const float* __restrict__ B,
          const float* __restrict__ bias, const float* __restrict__ pos,
          float* __restrict__ outF, int Ntot)
{
    extern __shared__ char smem[];
    const uint32_t sb = smem_u32(smem);
    const int tid  = threadIdx.x;
    const int wid  = tid >> 5;
    const int lane = tid & 31;
    const int g    = lane >> 2;
    const int t4   = lane & 3;
    const int mi   = lane >> 3;
    const int lr   = lane & 7;
    const int wm   = wid & 3;
    const int wn   = wid >> 2;
    const int row0 = blockIdx.x * 128;
    const int col0 = blockIdx.y * 64;

    float acc[2][4][4];
#pragma unroll
    for (int i = 0; i < 2; i++)
#pragma unroll
        for (int j = 0; j < 4; j++)
#pragma unroll
            for (int k = 0; k < 4; k++) acc[i][j][k] = 0.f;

    auto issue = [&](int st) {
        const int k0 = st * 32;
        const uint32_t base = sb + (st & 1) * TSTAGE;
#pragma unroll
        for (int z = 0; z < 4; z++) {
            const int idx = tid + z * 256;       // 0..1023
            const int r = idx >> 3, c = idx & 7;
            CPASYNC(base + TSA + r * PITCHB + c * 16,
                    A + (size_t)(row0 + r) * KK + k0 + c * 4);
        }
#pragma unroll
        for (int z = 0; z < 2; z++) {
            const int idx = tid + z * 256;       // 0..511
            const int r = idx >> 3, c = idx & 7;
            CPASYNC(base + TSB + r * PITCHB + c * 16,
                    B + (size_t)(col0 + r) * KK + k0 + c * 4);
        }
    };

    issue(0);
    CPCOMMIT();

#pragma unroll 1
    for (int st = 0; st < 8; st++) {
        if (st < 7) { issue(st + 1); CPCOMMIT(); CPWAIT1(); }
        else        { CPWAIT0(); }
        __syncthreads();

        const uint32_t base = sb + (st & 1) * TSTAGE;
#pragma unroll
        for (int s = 0; s < 4; s++) {       // 4 k8-steps per 32-k stage
            uint32_t af[2][4];
#pragma unroll
            for (int mt = 0; mt < 2; mt++) {
                const uint32_t arow = (uint32_t)(wm * 32 + mt * 16 + (mi & 1) * 8 + lr);
                ldsm_x4(af[mt], base + TSA + arow * PITCHB + s * 32 + (mi >> 1) * 16);
            }
            uint32_t bf[2][4];
#pragma unroll
            for (int nt2 = 0; nt2 < 2; nt2++) {
                const uint32_t brow = (uint32_t)(wn * 32 + nt2 * 16 + (mi & 1) * 8 + lr);
                ldsm_x4(bf[nt2], base + TSB + brow * PITCHB + s * 32 + (mi >> 1) * 16);
            }
#pragma unroll
            for (int mt = 0; mt < 2; mt++)
#pragma unroll
                for (int nt = 0; nt < 4; nt++) {
                    uint32_t bb[2] = { bf[nt >> 1][nt & 1], bf[nt >> 1][(nt & 1) + 2] };
                    mma_tf32(acc[mt][nt], af[mt], bb);
                }
        }
        __syncthreads();
    }

    // ---- epilogue: bias (+pos|+relu), tf32-round, store ----
#pragma unroll
    for (int mt = 0; mt < 2; mt++) {
#pragma unroll
        for (int nt = 0; nt < 4; nt++) {
            const int c = col0 + wn * 32 + nt * 8 + t4 * 2;
            const float b0 = bias[c], b1 = bias[c + 1];
#pragma unroll
            for (int half = 0; half < 2; half++) {
                const int r = row0 + wm * 32 + mt * 16 + g + half * 8;
                float v0 = acc[mt][nt][half * 2 + 0] + b0;
                float v1 = acc[mt][nt][half * 2 + 1] + b1;
                if (EPI == 2) { v0 = fmaxf(v0, 0.f); v1 = fmaxf(v1, 0.f); }
                if (EPI == 1) {
                    const int s = r % SS;
                    v0 += pos[s * DD + c];
                    v1 += pos[s * DD + c + 1];
                }
                const size_t o = (size_t)r * Ntot + c;
                *(float2*)(outF + o) = make_float2(tf32r(v0), tf32r(v1));
            }
        }
    }
}

// ======================= prep kernels ======================================
__global__ void round_src_kernel(const float* __restrict__ in,
                                 float* __restrict__ out, int n)
{
    const int i = blockIdx.x * blockDim.x + threadIdx.x;
    if (i < n) out[i] = tf32r(in[i]);
}

__global__ void round_weights_kernel(const float* __restrict__ enc,
                                     const float* __restrict__ qkvw,
                                     const float* __restrict__ outw,
                                     const float* __restrict__ l1,
                                     const float* __restrict__ l2,
                                     float* __restrict__ dst)
{
    const int i = blockIdx.x * blockDim.x + threadIdx.x;
    if (i >= WTOTAL) return;
    float v;
    if      (i < WOFF_QKV) v = enc [i - WOFF_ENC];
    else if (i < WOFF_OUT) v = qkvw[i - WOFF_QKV];
    else if (i < WOFF_L1)  v = outw[i - WOFF_OUT];
    else if (i < WOFF_L2)  v = l1  [i - WOFF_L1];
    else                   v = l2  [i - WOFF_L2];
    dst[i] = tf32r(v);
}

__global__ void pos_kernel(float* __restrict__ pos)
{
    const int s = blockIdx.x;       // 0..SS-1
    const int d = threadIdx.x;      // 0..255
    const int p = d >> 1;
    const float div = expf(-(float)(2 * p) * 0.03597789207803197f);
    const float ang = (float)s * div;
    pos[s * DD + d] = (d & 1) ? cosf(ang) : sinf(ang);
}

// ======================= flash-style banded attention =======================
// Block: one (b,h) x 64 queries, 4 warps (16 rows each).
// Keys jj in [0,192), j_abs = i0-99+jj, 3 tiles of 64.
// QK and PV bf16 hi/lo 3-pass mma; running softmax in registers.
#define FQH 0
#define FQL 17408
#define FKH 34816
#define FKL 52224
#define FVH 69632
#define FVL 88064
#define FSM_TOTAL 106496

__global__ void __launch_bounds__(128)
flash_attn_kernel(const float* __restrict__ qkv, float* __restrict__ ctxp)
{
    extern __shared__ char sm[];
    const uint32_t sb = smem_u32(sm);
    const int tid  = threadIdx.x;
    const int w    = tid >> 5;
    const int lane = tid & 31;
    const int g    = lane >> 2;
    const int t4   = lane & 3;
    const int mi   = lane >> 3;
    const int lr   = lane & 7;

    const int i0 = blockIdx.x * 64;
    const int b  = blockIdx.y >> 1;
    const int h  = blockIdx.y & 1;
    const int kstart = i0 - 99;
    const float* base = qkv + (size_t)b * SS * 768;

    // ---- load Q (scaled) -> smem hi/lo, pitch 136 elems ----
    {
        const int r  = tid >> 1;
        const int d0 = (tid & 1) * 64;
        const int i  = min(i0 + r, SS - 1);
        const float* qr = base + (size_t)i * 768 + h * 128 + d0;
        const uint32_t so = (uint32_t)r * 272 + (uint32_t)d0 * 2;
#pragma unroll
        for (int c = 0; c < 16; c++) {
            float4 v = *(const float4*)(qr + c * 4);
            v.x *= 0.08838834764831845f; v.y *= 0.08838834764831845f;
            v.z *= 0.08838834764831845f; v.w *= 0.08838834764831845f;
            uint32_t h0, l0, h1, l1;
            split2(v.x, v.y, h0, l0);
            split2(v.z, v.w, h1, l1);
            *(uint32_t*)(sm + FQH + so + c * 8)     = h0;
            *(uint32_t*)(sm + FQH + so + c * 8 + 4) = h1;
            *(uint32_t*)(sm + FQL + so + c * 8)     = l0;
            *(uint32_t*)(sm + FQL + so + c * 8 + 4) = l1;
        }
    }

    float ctx[16][4];
#pragma unroll
    for (int i = 0; i < 16; i++)
#pragma unroll
        for (int j = 0; j < 4; j++) ctx[i][j] = 0.f;

    const int qi0 = w * 16 + g;
    const int qi1 = qi0 + 8;
    const int vlo0 = max(qi0, 99 - i0), vhi0 = qi0 + 99;
    const int vlo1 = max(qi1, 99 - i0), vhi1 = qi1 + 99;
    float m0 = -1e30f, m1 = -1e30f, L0 = 0.f, L1 = 0.f;

#pragma unroll 1
    for (int tt = 0; tt < 3; tt++) {
        __syncthreads();
        // ---- K tile hi/lo ----
        {
            const int r  = tid >> 1;
            const int d0 = (tid & 1) * 64;
            const int j  = min(max(kstart + tt * 64 + r, 0), SS - 1);
            const float* kr = base + (size_t)j * 768 + 256 + h * 128 + d0;
            const uint32_t so = (uint32_t)r * 272 + (uint32_t)d0 * 2;
#pragma unroll
            for (int c = 0; c < 16; c++) {
                float4 v = *(const float4*)(kr + c * 4);
                uint32_t h0, l0, h1, l1;
                split2(v.x, v.y, h0, l0);
                split2(v.z, v.w, h1, l1);
                *(uint32_t*)(sm + FKH + so + c * 8)     = h0;
                *(uint32_t*)(sm + FKH + so + c * 8 + 4) = h1;
                *(uint32_t*)(sm + FKL + so + c * 8)     = l0;
                *(uint32_t*)(sm + FKL + so + c * 8 + 4) = l1;
            }
        }
        // ---- V tile transposed [d][j], pitch 72 elems ----
        {
            const int r  = tid >> 1;
            const int d0 = (tid & 1) * 64;
            const int j  = min(max(kstart + tt * 64 + r, 0), SS - 1);
            const float* vr = base + (size_t)j * 768 + 512 + h * 128 + d0;
#pragma unroll
            for (int c = 0; c < 16; c++) {
                float4 v = *(const float4*)(vr + c * 4);
                const float vv[4] = {v.x, v.y, v.z, v.w};
#pragma unroll
                for (int t = 0; t < 4; t++) {
                    const int d = d0 + c * 4 + t;
                    const __nv_bfloat16 hv = __float2bfloat16(vv[t]);
                    const __nv_bfloat16 lv = __float2bfloat16(vv[t] - __bfloat162float(hv));
                    *(__nv_bfloat16*)(sm + FVH + d * 144 + r * 2) = hv;
                    *(__nv_bfloat16*)(sm + FVL + d * 144 + r * 2) = lv;
                }
            }
        }
        __syncthreads();

        // ---- QK ----
        float S[8][4];
#pragma unroll
        for (int i = 0; i < 8; i++)
#pragma unroll
            for (int j = 0; j < 4; j++) S[i][j] = 0.f;

#pragma unroll
        for (int kb = 0; kb < 8; kb++) {
            uint32_t aqh[4], aql[4];
            const uint32_t arow = (uint32_t)(w * 16 + (mi & 1) * 8 + lr) * 272
                                + (uint32_t)(kb * 16 + (mi >> 1) * 8) * 2;
            ldsm_x4(aqh, sb + FQH + arow);
            ldsm_x4(aql, sb + FQL + arow);
#pragma unroll
            for (int nbp = 0; nbp < 4; nbp++) {
                uint32_t bkh[4], bkl[4];
                const uint32_t brow = (uint32_t)(nbp * 16 + (mi >> 1) * 8 + lr) * 272
                                    + (uint32_t)(kb * 16 + (mi & 1) * 8) * 2;
                ldsm_x4(bkh, sb + FKH + brow);
                ldsm_x4(bkl, sb + FKL + brow);
                mma_bf16(S[nbp * 2],     aqh, &bkh[0]);
                mma_bf16(S[nbp * 2 + 1], aqh, &bkh[2]);
                mma_bf16(S[nbp * 2],     aqh, &bkl[0]);
                mma_bf16(S[nbp * 2 + 1], aqh, &bkl[2]);
                mma_bf16(S[nbp * 2],     aql, &bkh[0]);
                mma_bf16(S[nbp * 2 + 1], aql, &bkh[2]);
            }
        }

        // ---- band mask + running softmax ----
        float mx0 = -1e30f, mx1 = -1e30f;
#pragma unroll
        for (int nb = 0; nb < 8; nb++) {
            const int jj = tt * 64 + nb * 8 + t4 * 2;
            if (jj < vlo0     || jj > vhi0)     S[nb][0] = -1e30f;
            if (jj + 1 < vlo0 || jj + 1 > vhi0) S[nb][1] = -1e30f;
            if (jj < vlo1     || jj > vhi1)     S[nb][2] = -1e30f;
            if (jj + 1 < vlo1 || jj + 1 > vhi1) S[nb][3] = -1e30f;
            mx0 = fmaxf(mx0, fmaxf(S[nb][0], S[nb][1]));
            mx1 = fmaxf(mx1, fmaxf(S[nb][2], S[nb][3]));
        }
        mx0 = fmaxf(mx0, __shfl_xor_sync(0xffffffffu, mx0, 1));
        mx0 = fmaxf(mx0, __shfl_xor_sync(0xffffffffu, mx0, 2));
        mx1 = fmaxf(mx1, __shfl_xor_sync(0xffffffffu, mx1, 1));
        mx1 = fmaxf(mx1, __shfl_xor_sync(0xffffffffu, mx1, 2));

        const float mn0 = fmaxf(m0, mx0);
        const float mn1 = fmaxf(m1, mx1);
        const float f0 = __expf(m0 - mn0);
        const float f1 = __expf(m1 - mn1);

        float sum0 = 0.f, sum1 = 0.f;
#pragma unroll
        for (int nb = 0; nb < 8; nb++) {
            float e0 = (S[nb][0] == -1e30f) ? 0.f : __expf(S[nb][0] - mn0);
            float e1 = (S[nb][1] == -1e30f) ? 0.f : __expf(S[nb][1] - mn0);
            float e2 = (S[nb][2] == -1e30f) ? 0.f : __expf(S[nb][2] - mn1);
            float e3 = (S[nb][3] == -1e30f) ? 0.f : __expf(S[nb][3] - mn1);
            S[nb][0] = e0; S[nb][1] = e1; S[nb][2] = e2; S[nb][3] = e3;
            sum0 += e0 + e1;
            sum1 += e2 + e3;
        }
        sum0 += __shfl_xor_sync(0xffffffffu, sum0, 1);
        sum0 += __shfl_xor_sync(0xffffffffu, sum0, 2);
        sum1 += __shfl_xor_sync(0xffffffffu, sum1, 1);
        sum1 += __shfl_xor_sync(0xffffffffu, sum1, 2);
        L0 = L0 * f0 + sum0;
        L1 = L1 * f1 + sum1;
        m0 = mn0; m1 = mn1;

#pragma unroll
        for (int nb = 0; nb < 16; nb++) {
            ctx[nb][0] *= f0; ctx[nb][1] *= f0;
            ctx[nb][2] *= f1; ctx[nb][3] *= f1;
        }

        // ---- PV ----
#pragma unroll
        for (int kb2 = 0; kb2 < 4; kb2++) {
            uint32_t ahi[4], alo[4];
            split2(S[2 * kb2][0],     S[2 * kb2][1],     ahi[0], alo[0]);
            split2(S[2 * kb2][2],     S[2 * kb2][3],     ahi[1], alo[1]);
            split2(S[2 * kb2 + 1][0], S[2 * kb2 + 1][1], ahi[2], alo[2]);
            split2(S[2 * kb2 + 1][2], S[2 * kb2 + 1][3], ahi[3], alo[3]);
#pragma unroll
            for (int dbp = 0; dbp < 8; dbp++) {
                uint32_t bvh[4], bvl[4];
                const uint32_t vrow = (uint32_t)(dbp * 16 + (mi >> 1) * 8 + lr) * 144
                                    + (uint32_t)(kb2 * 16 + (mi & 1) * 8) * 2;
                ldsm_x4(bvh, sb + FVH + vrow);
                ldsm_x4(bvl, sb + FVL + vrow);
                mma_bf16(ctx[dbp * 2],     ahi, &bvh[0]);
                mma_bf16(ctx[dbp * 2 + 1], ahi, &bvh[2]);
                mma_bf16(ctx[dbp * 2],     ahi, &bvl[0]);
                mma_bf16(ctx[dbp * 2 + 1], ahi, &bvl[2]);
                mma_bf16(ctx[dbp * 2],     alo, &bvh[0]);
                mma_bf16(ctx[dbp * 2 + 1], alo, &bvh[2]);
            }
        }
    }

    // ---- store ctx (tf32-rounded fp32) ----
    const float inv0 = 1.f / L0;
    const float inv1 = 1.f / L1;
    const int ig0 = i0 + qi0;
    const int ig1 = i0 + qi1;
    if (ig0 < SS) {
        const size_t ro = (size_t)(b * SS + ig0) * DD + h * HDIM;
#pragma unroll
        for (int nb = 0; nb < 16; nb++) {
            const int d = nb * 8 + t4 * 2;
            *(float2*)(ctxp + ro + d) =
                make_float2(tf32r(ctx[nb][0] * inv0), tf32r(ctx[nb][1] * inv0));
        }
    }
    if (ig1 < SS) {
        const size_t ro = (size_t)(b * SS + ig1) * DD + h * HDIM;
#pragma unroll
        for (int nb = 0; nb < 16; nb++) {
            const int d = nb * 8 + t4 * 2;
            *(float2*)(ctxp + ro + d) =
                make_float2(tf32r(ctx[nb][2] * inv1), tf32r(ctx[nb][3] * inv1));
        }
    }
}

// ---------------- residual add + layernorm (rounded fp32 out) --------------
__global__ void __launch_bounds__(256)
add_ln_kernel(const float* __restrict__ x, const float* __restrict__ y,
              const float* __restrict__ w, const float* __restrict__ b,
              float* __restrict__ out)
{
    const int row = blockIdx.x;
    const int t   = threadIdx.x;
    const size_t idx = (size_t)row * DD + t;
    const float v = x[idx] + y[idx];

    __shared__ float s1[8], s2[8];
    float r = v, q = v * v;
#pragma unroll
    for (int o = 16; o; o >>= 1) {
        r += __shfl_xor_sync(0xffffffffu, r, o);
        q += __shfl_xor_sync(0xffffffffu, q, o);
    }
    if ((t & 31) == 0) { s1[t >> 5] = r; s2[t >> 5] = q; }
    __syncthreads();
    float tot  = s1[0]+s1[1]+s1[2]+s1[3]+s1[4]+s1[5]+s1[6]+s1[7];
    float tot2 = s2[0]+s2[1]+s2[2]+s2[3]+s2[4]+s2[5]+s2[6]+s2[7];
    const float mean = tot * (1.f / DD);
    const float var  = tot2 * (1.f / DD) - mean * mean;
    const float inv  = rsqrtf(var + 1e-5f);

    out[idx] = tf32r((v - mean) * inv * w[t] + b[t]);
}

// ---------------- fused output head ----------------------------------------
__global__ void head_prep_kernel(const float* __restrict__ fc1_w,
                                 const float* __restrict__ fc1_b,
                                 const float* __restrict__ fc2_w,
                                 const float* __restrict__ fc2_b,
                                 float* __restrict__ wc)
{
    const int d = threadIdx.x;
    float s = 0.f;
#pragma unroll
    for (int j = 0; j < 64; j++) s += fc2_w[j] * fc1_w[j * DD + d];
    wc[d] = s;
    if (d == 0) {
        float bb = fc2_b[0];
        for (int j = 0; j < 64; j++) bb += fc2_w[j] * fc1_b[j];
        wc[256] = bb;
    }
}

__global__ void __launch_bounds__(256)
head_gemv_kernel(const float* __restrict__ h2, const float* __restrict__ wc,
                 float* __restrict__ out)
{
    const int warp = (blockIdx.x * blockDim.x + threadIdx.x) >> 5;
    const int lane = threadIdx.x & 31;
    if (warp >= MM) return;
    const float* r = h2 + (size_t)warp * DD;
    float s = 0.f;
#pragma unroll
    for (int c = 0; c < 8; c++) s += r[lane + 32 * c] * wc[lane + 32 * c];
#pragma unroll
    for (int o = 16; o; o >>= 1) s += __shfl_xor_sync(0xffffffffu, s, o);
    if (lane == 0) out[warp] = s + wc[256];
}

// ---------------- host launch -----------------------------------------------
template<typename T>
static T* dptr(const void* sym) {
    void* p = nullptr;
    cudaGetSymbolAddress(&p, sym);
    return (T*)p;
}

extern "C" void kernel_launch(void* const* d_in, const int* in_sizes, int n_in,
                              void* d_out, int out_size)
{
    const float* src        = (const float*)d_in[0];
    const float* W_enc      = (const float*)d_in[2];
    const float* b_enc      = (const float*)d_in[3];
    const float* in_proj_w  = (const float*)d_in[4];
    const float* in_proj_b  = (const float*)d_in[5];
    const float* out_proj_w = (const float*)d_in[6];
    const float* out_proj_b = (const float*)d_in[7];
    const float* ln1_w      = (const float*)d_in[8];
    const float* ln1_b      = (const float*)d_in[9];
    const float* lin1_w     = (const float*)d_in[10];
    const float* lin1_b     = (const float*)d_in[11];
    const float* lin2_w     = (const float*)d_in[12];
    const float* lin2_b     = (const float*)d_in[13];
    const float* ln2_w      = (const float*)d_in[14];
    const float* ln2_b      = (const float*)d_in[15];
    const float* fc1_w      = (const float*)d_in[16];
    const float* fc1_b      = (const float*)d_in[17];
    const float* fc2_w      = (const float*)d_in[18];
    const float* fc2_b      = (const float*)d_in[19];
    float* out = (float*)d_out;

    float* srcr = dptr<float>(g_src);
    float* x    = dptr<float>(g_x);
    float* qkv  = dptr<float>(g_qkv);
    float* ctx  = dptr<float>(g_ctx);
    float* att  = dptr<float>(g_att);
    float* h1   = dptr<float>(g_h1);
    float* ff   = dptr<float>(g_ff);
    float* ff2  = dptr<float>(g_ff2);
    float* h2   = dptr<float>(g_h2);
    float* wc   = dptr<float>(g_wc);
    float* pos  = dptr<float>(g_pos);
    float* w    = dptr<float>(g_w);

    cudaFuncSetAttribute(tf32_gemm<0>, cudaFuncAttributeMaxDynamicSharedMemorySize, TSM_TOTAL);
    cudaFuncSetAttribute(tf32_gemm<1>, cudaFuncAttributeMaxDynamicSharedMemorySize, TSM_TOTAL);
    cudaFuncSetAttribute(tf32_gemm<2>, cudaFuncAttributeMaxDynamicSharedMemorySize, TSM_TOTAL);
    cudaFuncSetAttribute(flash_attn_kernel, cudaFuncAttributeMaxDynamicSharedMemorySize, FSM_TOTAL);

    const dim3 blk(256);

    // prep
    round_weights_kernel<<<(WTOTAL + 255)/256, blk>>>(W_enc, in_proj_w, out_proj_w,
                                                      lin1_w, lin2_w, w);
    round_src_kernel<<<(MM*DD + 255)/256, blk>>>(src, srcr, MM*DD);
    pos_kernel<<<SS, blk>>>(pos);
    head_prep_kernel<<<1, 256>>>(fc1_w, fc1_b, fc2_w, fc2_b, wc);

    // 1. encoder projection + pos -> x
    tf32_gemm<1><<<dim3(MM/128, DD/64), blk, TSM_TOTAL>>>(
        srcr, w + WOFF_ENC, b_enc, pos, x, DD);
    // 2. qkv projection
    tf32_gemm<0><<<dim3(MM/128, (3*DD)/64), blk, TSM_TOTAL>>>(
        x, w + WOFF_QKV, in_proj_b, nullptr, qkv, 3*DD);
    // 3. flash banded attention -> ctx
    flash_attn_kernel<<<dim3(32, BB*HH), 128, FSM_TOTAL>>>(qkv, ctx);
    // 4. output projection
    tf32_gemm<0><<<dim3(MM/128, DD/64), blk, TSM_TOTAL>>>(
        ctx, w + WOFF_OUT, out_proj_b, nullptr, att, DD);
    // 5. add + LN1
    add_ln_kernel<<<MM, blk>>>(x, att, ln1_w, ln1_b, h1);
    // 6. ffn1 + relu
    tf32_gemm<2><<<dim3(MM/128, FFN/64), blk, TSM_TOTAL>>>(
        h1, w + WOFF_L1, lin1_b, nullptr, ff, FFN);
    // 7. ffn2
    tf32_gemm<0><<<dim3(MM/128, DD/64), blk, TSM_TOTAL>>>(
        ff, w + WOFF_L2, lin2_b, nullptr, ff2, DD);
    // 8. add + LN2
    add_ln_kernel<<<MM, blk>>>(h1, ff2, ln2_w, ln2_b, h2);
    // 9. fused head -> logits [B,S]
    head_gemv_kernel<<<(MM * 32 + 255) / 256, blk>>>(h2, wc, out);
}